// round 2
// baseline (speedup 1.0000x reference)
#include <cuda_runtime.h>
#include <cuda_bf16.h>
#include <math_constants.h>

// Problem constants (fixed by the dataset)
#define CC   64
#define NB   2048
#define NT   20
#define NN   (NB * NT)          // 40960 nodes
#define NE   1310720            // edges
#define CHUNK 16                // edges per warp inner tile
#define HSTRIDE 24              // float2 stride per k-row in smem (16B-aligned rows)

// -------- persistent device scratch (static allocation is allowed) --------
__device__ float  g_u[NN * CC];        // x @ (W1a - W1b)^T + b1
__device__ float  g_v[NN * CC];        // x @ W1b^T
__device__ int    g_deg[NN];
__device__ int    g_rowptr[NN + 1];
__device__ int    g_cursor[NN];
__device__ int    g_ss[NE];            // edge sources sorted by dst (CSR)
__device__ float2 g_w2p[64 * 64];      // [k][l] = (W2[l,k], W2[l+32,k])
__device__ int    g_is64;              // edge_index dtype flag (1 = int64, 0 = int32)

// ---------------- dtype detection: int32 vs int64 edge_index ----------------
// int64 layout: words = [lo0, hi0, lo1, hi1, ...], hi words all 0 (values < 2^31).
// int32 layout: words = src values, random in [0, NN) -> odd words almost surely nonzero.
__global__ void __launch_bounds__(1024) k_detect(const int* __restrict__ w) {
    __shared__ int flag32;
    if (threadIdx.x == 0) flag32 = 0;
    __syncthreads();
    if (w[2 * threadIdx.x + 1] != 0) atomicOr(&flag32, 1);
    __syncthreads();
    if (threadIdx.x == 0) g_is64 = flag32 ? 0 : 1;
}

__device__ __forceinline__ int load_idx(const void* ei, int pos, int is64) {
    if (is64) return (int)((const long long*)ei)[pos];
    return ((const int*)ei)[pos];
}

// ---------------- reset counters + build packed W2 ----------------
__global__ void __launch_bounds__(256) k_reset(const float* __restrict__ W2) {
    int i = blockIdx.x * 256 + threadIdx.x;
    if (i < NN) g_deg[i] = 0;
    if (i < 64 * 64) {
        int k = i >> 6, l = i & 63;
        g_w2p[i] = make_float2(W2[l * 64 + k], W2[(l + 32) * 64 + k]);
    }
}

// ---------------- per-node transform: u, v ----------------
// block = (64, 4) threads, 16 nodes per block (4 nodes per thread)
__global__ void __launch_bounds__(256) k_node(
    const float* __restrict__ x, const float* __restrict__ W1,
    const float* __restrict__ b1)
{
    __shared__ float W1s[64 * 129];   // padded rows: conflict-free LDS
    __shared__ float xs[16 * 64];
    int tid = threadIdx.x + threadIdx.y * 64;
    for (int i = tid; i < 64 * 128; i += 256) {
        int c = i >> 7, k2 = i & 127;
        W1s[c * 129 + k2] = W1[i];
    }
    int node0 = blockIdx.x * 16;
    for (int i = tid; i < 16 * 64; i += 256)
        xs[i] = x[node0 * 64 + i];
    __syncthreads();

    int c = threadIdx.x;       // output channel
    int g = threadIdx.y;       // node group (4 nodes each)
    float ua[4] = {0.f, 0.f, 0.f, 0.f};
    float vb[4] = {0.f, 0.f, 0.f, 0.f};
    #pragma unroll 8
    for (int k = 0; k < 64; k++) {
        float wa = W1s[c * 129 + k];
        float wb = W1s[c * 129 + 64 + k];
        #pragma unroll
        for (int j = 0; j < 4; j++) {
            float xk = xs[(g * 4 + j) * 64 + k];   // warp-broadcast
            ua[j] = fmaf(xk, wa, ua[j]);
            vb[j] = fmaf(xk, wb, vb[j]);
        }
    }
    float bc = b1[c];
    #pragma unroll
    for (int j = 0; j < 4; j++) {
        int n = node0 + g * 4 + j;
        g_u[n * 64 + c] = ua[j] - vb[j] + bc;  // fold b1 into u
        g_v[n * 64 + c] = vb[j];
    }
}

// ---------------- degree histogram ----------------
__global__ void __launch_bounds__(256) k_hist(const void* __restrict__ ei) {
    int e = blockIdx.x * 256 + threadIdx.x;
    int is64 = g_is64;
    if (e < NE) {
        int dst = load_idx(ei, NE + e, is64);
        if ((unsigned)dst < NN) atomicAdd(&g_deg[dst], 1);
    }
}

// ---------------- exclusive scan (single block; 40960 = 1024*40) ----------------
__global__ void __launch_bounds__(1024) k_scan() {
    __shared__ int sums[1024];
    int t = threadIdx.x;
    int base = t * 40;
    int s = 0;
    for (int i = 0; i < 40; i++) s += g_deg[base + i];
    sums[t] = s;
    __syncthreads();
    for (int off = 1; off < 1024; off <<= 1) {
        int a = sums[t];
        int b = (t >= off) ? sums[t - off] : 0;
        __syncthreads();
        sums[t] = a + b;
        __syncthreads();
    }
    int run = (t > 0) ? sums[t - 1] : 0;
    for (int i = 0; i < 40; i++) {
        g_rowptr[base + i] = run;
        g_cursor[base + i] = run;
        run += g_deg[base + i];
    }
    if (t == 1023) g_rowptr[NN] = run;
}

// ---------------- scatter edges into CSR buckets ----------------
__global__ void __launch_bounds__(256) k_scatter(const void* __restrict__ ei) {
    int e = blockIdx.x * 256 + threadIdx.x;
    int is64 = g_is64;
    if (e < NE) {
        int dst = load_idx(ei, NE + e, is64);
        int src = load_idx(ei, e, is64);
        if ((unsigned)dst < NN && (unsigned)src < NN) {
            int p = atomicAdd(&g_cursor[dst], 1);
            g_ss[p] = src;
        }
    }
}

// ---------------- hot kernel: per-dst edge GEMM + max + residual ReLU ----------------
// one warp per dst node; lane l owns output channels (l, l+32) as an f32x2 pair
__global__ void __launch_bounds__(128) k_edge(
    const float* __restrict__ x, const float* __restrict__ b2,
    float* __restrict__ out)
{
    __shared__ __align__(16) float2 hT[4 * 64 * HSTRIDE];   // 48KB: per-warp h tiles
    int w = threadIdx.x >> 5;
    int l = threadIdx.x & 31;
    int node = blockIdx.x * 4 + w;
    float2* hw = hT + w * 64 * HSTRIDE;

    int beg = g_rowptr[node];
    int end = g_rowptr[node + 1];
    float u0 = g_u[node * 64 + l];
    float u1 = g_u[node * 64 + 32 + l];
    float acc0 = -CUDART_INF_F, acc1 = -CUDART_INF_F;

    for (int cb = beg; cb < end; cb += CHUNK) {
        int cnt = min(CHUNK, end - cb);
        // --- phase 1: gather v, compute h = lrelu(u+v), store splatted pairs ---
        #pragma unroll
        for (int e = 0; e < CHUNK; e++) {
            int idx = (e < cnt) ? (cb + e) : cb;   // always in-bounds
            int src = g_ss[idx];                   // warp-uniform broadcast load
            float v0 = g_v[src * 64 + l];
            float v1 = g_v[src * 64 + 32 + l];
            float h0 = u0 + v0; h0 = fmaxf(h0, 0.01f * h0);
            float h1 = u1 + v1; h1 = fmaxf(h1, 0.01f * h1);
            hw[l * HSTRIDE + e]        = make_float2(h0, h0);
            hw[(l + 32) * HSTRIDE + e] = make_float2(h1, h1);
        }
        __syncwarp();
        // --- phase 2: msg = h @ W2^T via packed f32x2 FMA ---
        unsigned long long s[CHUNK];
        #pragma unroll
        for (int e = 0; e < CHUNK; e++) s[e] = 0ULL;   // {+0.f,+0.f}
        #pragma unroll 4
        for (int k = 0; k < 64; k++) {
            unsigned long long wk =
                __ldg(reinterpret_cast<const unsigned long long*>(g_w2p) + k * 64 + l);
            const ulonglong2* hr =
                reinterpret_cast<const ulonglong2*>(hw + k * HSTRIDE);
            #pragma unroll
            for (int p = 0; p < CHUNK / 2; p++) {
                ulonglong2 hq = hr[p];   // broadcast LDS.128 (same 16B for all lanes)
                asm("fma.rn.f32x2 %0, %1, %2, %0;" : "+l"(s[2 * p])     : "l"(hq.x), "l"(wk));
                asm("fma.rn.f32x2 %0, %1, %2, %0;" : "+l"(s[2 * p + 1]) : "l"(hq.y), "l"(wk));
            }
        }
        // --- phase 3: running max over valid edges ---
        #pragma unroll
        for (int e = 0; e < CHUNK; e++) {
            if (e < cnt) {
                float2 sf = *reinterpret_cast<float2*>(&s[e]);
                acc0 = fmaxf(acc0, sf.x);
                acc1 = fmaxf(acc1, sf.y);
            }
        }
        __syncwarp();
    }

    float a0 = (end > beg) ? (acc0 + b2[l])      : 0.0f;  // empty segment -> 0
    float a1 = (end > beg) ? (acc1 + b2[32 + l]) : 0.0f;
    float o0 = a0 + x[node * 64 + l];
    float o1 = a1 + x[node * 64 + 32 + l];
    out[node * 64 + l]      = fmaxf(o0, 0.0f);
    out[node * 64 + 32 + l] = fmaxf(o1, 0.0f);
}

// ---------------- launch ----------------
extern "C" void kernel_launch(void* const* d_in, const int* in_sizes, int n_in,
                              void* d_out, int out_size) {
    const float* x  = (const float*)d_in[0];
    const void*  ei = d_in[1];
    const float* W1 = (const float*)d_in[2];
    const float* b1 = (const float*)d_in[3];
    const float* W2 = (const float*)d_in[4];
    const float* b2 = (const float*)d_in[5];
    float* out = (float*)d_out;

    k_detect <<<1, 1024>>>((const int*)ei);
    k_reset  <<<(NN + 255) / 256, 256>>>(W2);
    k_node   <<<NN / 16, dim3(64, 4)>>>(x, W1, b1);
    k_hist   <<<NE / 256, 256>>>(ei);
    k_scan   <<<1, 1024>>>();
    k_scatter<<<NE / 256, 256>>>(ei);
    k_edge   <<<NN / 4, 128>>>(x, b2, out);
}

// round 3
// speedup vs baseline: 1.3670x; 1.3670x over previous
#include <cuda_runtime.h>
#include <cuda_bf16.h>
#include <math_constants.h>

// Problem constants (fixed by the dataset)
#define CC   64
#define NB   2048
#define NT   20
#define NN   (NB * NT)          // 40960 nodes
#define NE   1310720            // edges
#define CHUNK 16                // edges per warp inner tile
#define HSTRIDE 20              // float stride per k-row in smem (80B: 16B-aligned, 4-way STS conflict only)

typedef unsigned long long ull;

// -------- persistent device scratch (static allocation is allowed) --------
__device__ float  g_u[NN * CC];        // x @ (W1a - W1b)^T + b1
__device__ float  g_v[NN * CC];        // x @ W1b^T
__device__ int    g_deg[NN];
__device__ int    g_rowptr[NN + 1];
__device__ int    g_cursor[NN];
__device__ int    g_ss[NE];            // edge sources sorted by dst (CSR)
__device__ ull    g_w2a[64 * 32];      // [k][l] = splat2(W2[l,k])
__device__ ull    g_w2b[64 * 32];      // [k][l] = splat2(W2[l+32,k])
__device__ int    g_is64;              // edge_index dtype flag (1 = int64, 0 = int32)

// ---------------- dtype detection: int32 vs int64 edge_index ----------------
__global__ void __launch_bounds__(1024) k_detect(const int* __restrict__ w) {
    __shared__ int flag32;
    if (threadIdx.x == 0) flag32 = 0;
    __syncthreads();
    if (w[2 * threadIdx.x + 1] != 0) atomicOr(&flag32, 1);
    __syncthreads();
    if (threadIdx.x == 0) g_is64 = flag32 ? 0 : 1;
}

__device__ __forceinline__ int load_idx(const void* ei, int pos, int is64) {
    if (is64) return (int)((const long long*)ei)[pos];
    return ((const int*)ei)[pos];
}

__device__ __forceinline__ ull splat2(float f) {
    ull r;
    unsigned u = __float_as_uint(f);
    asm("mov.b64 %0, {%1, %1};" : "=l"(r) : "r"(u));
    return r;
}

// ---------------- reset counters + build splatted W2 tables ----------------
__global__ void __launch_bounds__(256) k_reset(const float* __restrict__ W2) {
    int i = blockIdx.x * 256 + threadIdx.x;
    if (i < NN) g_deg[i] = 0;
    if (i < 64 * 32) {
        int k = i >> 5, l = i & 31;
        g_w2a[i] = splat2(W2[l * 64 + k]);
        g_w2b[i] = splat2(W2[(l + 32) * 64 + k]);
    }
}

// ---------------- per-node transform: u, v ----------------
__global__ void __launch_bounds__(256) k_node(
    const float* __restrict__ x, const float* __restrict__ W1,
    const float* __restrict__ b1)
{
    __shared__ float W1s[64 * 129];   // padded rows: conflict-free LDS
    __shared__ float xs[16 * 64];
    int tid = threadIdx.x + threadIdx.y * 64;
    for (int i = tid; i < 64 * 128; i += 256) {
        int c = i >> 7, k2 = i & 127;
        W1s[c * 129 + k2] = W1[i];
    }
    int node0 = blockIdx.x * 16;
    for (int i = tid; i < 16 * 64; i += 256)
        xs[i] = x[node0 * 64 + i];
    __syncthreads();

    int c = threadIdx.x;       // output channel
    int g = threadIdx.y;       // node group (4 nodes each)
    float ua[4] = {0.f, 0.f, 0.f, 0.f};
    float vb[4] = {0.f, 0.f, 0.f, 0.f};
    #pragma unroll 8
    for (int k = 0; k < 64; k++) {
        float wa = W1s[c * 129 + k];
        float wb = W1s[c * 129 + 64 + k];
        #pragma unroll
        for (int j = 0; j < 4; j++) {
            float xk = xs[(g * 4 + j) * 64 + k];   // warp-broadcast
            ua[j] = fmaf(xk, wa, ua[j]);
            vb[j] = fmaf(xk, wb, vb[j]);
        }
    }
    float bc = b1[c];
    #pragma unroll
    for (int j = 0; j < 4; j++) {
        int n = node0 + g * 4 + j;
        g_u[n * 64 + c] = ua[j] - vb[j] + bc;  // fold b1 into u
        g_v[n * 64 + c] = vb[j];
    }
}

// ---------------- degree histogram ----------------
__global__ void __launch_bounds__(256) k_hist(const void* __restrict__ ei) {
    int e = blockIdx.x * 256 + threadIdx.x;
    int is64 = g_is64;
    if (e < NE) {
        int dst = load_idx(ei, NE + e, is64);
        if ((unsigned)dst < NN) atomicAdd(&g_deg[dst], 1);
    }
}

// ---------------- exclusive scan (single block; 40960 = 1024*40) ----------------
__global__ void __launch_bounds__(1024) k_scan() {
    __shared__ int sums[1024];
    int t = threadIdx.x;
    int base = t * 40;
    int s = 0;
    for (int i = 0; i < 40; i++) s += g_deg[base + i];
    sums[t] = s;
    __syncthreads();
    for (int off = 1; off < 1024; off <<= 1) {
        int a = sums[t];
        int b = (t >= off) ? sums[t - off] : 0;
        __syncthreads();
        sums[t] = a + b;
        __syncthreads();
    }
    int run = (t > 0) ? sums[t - 1] : 0;
    for (int i = 0; i < 40; i++) {
        g_rowptr[base + i] = run;
        g_cursor[base + i] = run;
        run += g_deg[base + i];
    }
    if (t == 1023) g_rowptr[NN] = run;
}

// ---------------- scatter edges into CSR buckets ----------------
__global__ void __launch_bounds__(256) k_scatter(const void* __restrict__ ei) {
    int e = blockIdx.x * 256 + threadIdx.x;
    int is64 = g_is64;
    if (e < NE) {
        int dst = load_idx(ei, NE + e, is64);
        int src = load_idx(ei, e, is64);
        if ((unsigned)dst < NN && (unsigned)src < NN) {
            int p = atomicAdd(&g_cursor[dst], 1);
            g_ss[p] = src;
        }
    }
}

// ---------------- hot kernel: per-dst edge GEMM + max + residual ReLU ----------------
// One warp per dst node. Lane l owns output channels (l, l+32).
// h is stored UN-splatted in smem rows [k][e]; f32x2 packing pairs edges (e,e+1),
// W2 is pre-splatted {w,w} in L1-resident tables.
__global__ void __launch_bounds__(128) k_edge(
    const float* __restrict__ x, const float* __restrict__ b2,
    float* __restrict__ out)
{
    __shared__ __align__(16) float hT[4 * 64 * HSTRIDE];   // 20KB: per-warp h tiles
    int w = threadIdx.x >> 5;
    int l = threadIdx.x & 31;
    int node = blockIdx.x * 4 + w;
    float* hw = hT + w * 64 * HSTRIDE;

    int beg = g_rowptr[node];
    int end = g_rowptr[node + 1];
    float u0 = g_u[node * 64 + l];
    float u1 = g_u[node * 64 + 32 + l];
    float acc0 = -CUDART_INF_F, acc1 = -CUDART_INF_F;

    for (int cb = beg; cb < end; cb += CHUNK) {
        int cnt = min(CHUNK, end - cb);
        // --- phase 1: gather v, compute h = lrelu(u+v) in registers ---
        float h0[CHUNK], h1[CHUNK];
        #pragma unroll
        for (int e = 0; e < CHUNK; e++) {
            int idx = (e < cnt) ? (cb + e) : cb;   // always in-bounds
            int src = g_ss[idx];                   // warp-uniform broadcast load
            float v0 = g_v[src * 64 + l];
            float v1 = g_v[src * 64 + 32 + l];
            float t0 = u0 + v0; h0[e] = fmaxf(t0, 0.01f * t0);
            float t1 = u1 + v1; h1[e] = fmaxf(t1, 0.01f * t1);
        }
        // store rows k=l and k=l+32 (4-way conflict max: 20l mod 32 has period 8)
        float4* row0 = reinterpret_cast<float4*>(hw + l * HSTRIDE);
        float4* row1 = reinterpret_cast<float4*>(hw + (l + 32) * HSTRIDE);
        #pragma unroll
        for (int q = 0; q < 4; q++) {
            row0[q] = make_float4(h0[4 * q], h0[4 * q + 1], h0[4 * q + 2], h0[4 * q + 3]);
            row1[q] = make_float4(h1[4 * q], h1[4 * q + 1], h1[4 * q + 2], h1[4 * q + 3]);
        }
        __syncwarp();

        // --- phase 2: msg = h @ W2^T via packed f32x2 FMA, edges paired ---
        ull s0[CHUNK / 2], s1[CHUNK / 2];
        #pragma unroll
        for (int p = 0; p < CHUNK / 2; p++) { s0[p] = 0ULL; s1[p] = 0ULL; }
        #pragma unroll 4
        for (int k = 0; k < 64; k++) {
            ull wk0 = __ldg(g_w2a + k * 32 + l);   // {W2[l,k], W2[l,k]}
            ull wk1 = __ldg(g_w2b + k * 32 + l);   // {W2[l+32,k], W2[l+32,k]}
            const ulonglong2* hr = reinterpret_cast<const ulonglong2*>(hw + k * HSTRIDE);
            #pragma unroll
            for (int q = 0; q < 4; q++) {
                ulonglong2 hq = hr[q];   // broadcast LDS.128: h[k][4q..4q+3]
                asm("fma.rn.f32x2 %0, %1, %2, %0;" : "+l"(s0[2 * q])     : "l"(hq.x), "l"(wk0));
                asm("fma.rn.f32x2 %0, %1, %2, %0;" : "+l"(s0[2 * q + 1]) : "l"(hq.y), "l"(wk0));
                asm("fma.rn.f32x2 %0, %1, %2, %0;" : "+l"(s1[2 * q])     : "l"(hq.x), "l"(wk1));
                asm("fma.rn.f32x2 %0, %1, %2, %0;" : "+l"(s1[2 * q + 1]) : "l"(hq.y), "l"(wk1));
            }
        }
        // --- phase 3: running max over valid edges ---
        #pragma unroll
        for (int p = 0; p < CHUNK / 2; p++) {
            float2 a = *reinterpret_cast<float2*>(&s0[p]);
            float2 b = *reinterpret_cast<float2*>(&s1[p]);
            if (2 * p < cnt)     { acc0 = fmaxf(acc0, a.x); acc1 = fmaxf(acc1, b.x); }
            if (2 * p + 1 < cnt) { acc0 = fmaxf(acc0, a.y); acc1 = fmaxf(acc1, b.y); }
        }
        __syncwarp();
    }

    float a0 = (end > beg) ? (acc0 + b2[l])      : 0.0f;  // empty segment -> 0
    float a1 = (end > beg) ? (acc1 + b2[32 + l]) : 0.0f;
    float o0 = a0 + x[node * 64 + l];
    float o1 = a1 + x[node * 64 + 32 + l];
    out[node * 64 + l]      = fmaxf(o0, 0.0f);
    out[node * 64 + 32 + l] = fmaxf(o1, 0.0f);
}

// ---------------- launch ----------------
extern "C" void kernel_launch(void* const* d_in, const int* in_sizes, int n_in,
                              void* d_out, int out_size) {
    const float* x  = (const float*)d_in[0];
    const void*  ei = d_in[1];
    const float* W1 = (const float*)d_in[2];
    const float* b1 = (const float*)d_in[3];
    const float* W2 = (const float*)d_in[4];
    const float* b2 = (const float*)d_in[5];
    float* out = (float*)d_out;

    k_detect <<<1, 1024>>>((const int*)ei);
    k_reset  <<<(NN + 255) / 256, 256>>>(W2);
    k_node   <<<NN / 16, dim3(64, 4)>>>(x, W1, b1);
    k_hist   <<<NE / 256, 256>>>(ei);
    k_scan   <<<1, 1024>>>();
    k_scatter<<<NE / 256, 256>>>(ei);
    k_edge   <<<NN / 4, 128>>>(x, b2, out);
}

// round 5
// speedup vs baseline: 1.8099x; 1.3240x over previous
#include <cuda_runtime.h>
#include <cuda_bf16.h>
#include <math_constants.h>
#include <cstdint>

// Problem constants (fixed by the dataset)
#define CC    64
#define NB    2048
#define NT    20
#define NN    (NB * NT)          // 40960 nodes
#define NE    1310720            // edges
#define TILE_M 128               // edges per block tile (16 per warp)
#define NTILES (NE / TILE_M)     // 10240
#define EDGE_GRID 296            // persistent blocks (2 per SM)

// smem layout (dynamic, 16B aligned base)
#define ASTRIDE_B 272            // 136 bf16 per A row (128 data + 8 pad)
#define AOFF    0                // A_cat: 128 rows x [H_hi(64) | H_lo(64)] bf16  (34816 B)
#define BOFF    34816            // B: rows 0-63 = W_hi [n][k], rows 64-127 = W_lo (34816 B)
#define DSTOFF  69632            // int dst[128]
#define DYNSZ   70144
// D staging overlays A region: 128 rows x 68 fp32 (272 B/row)

#define AGG_EMPTY 0x80000000

// -------- persistent device scratch --------
__device__ __align__(16) float g_u[NN * CC];   // x @ (W1a - W1b)^T + b1
__device__ __align__(16) float g_v[NN * CC];   // x @ W1b^T
__device__ int   g_deg[NN];
__device__ int   g_rowptr[NN + 1];
__device__ int   g_cursor[NN];
__device__ int   g_ss[NE];             // edge src sorted by dst
__device__ int   g_sd[NE];             // edge dst sorted (non-decreasing)
__device__ int   g_agg[NN * CC];       // encoded-int max accumulator
__device__ int   g_is64;

// ---------------- dtype detection: int32 vs int64 edge_index ----------------
__global__ void __launch_bounds__(1024) k_detect(const int* __restrict__ w) {
    __shared__ int flag32;
    if (threadIdx.x == 0) flag32 = 0;
    __syncthreads();
    if (w[2 * threadIdx.x + 1] != 0) atomicOr(&flag32, 1);
    __syncthreads();
    if (threadIdx.x == 0) g_is64 = flag32 ? 0 : 1;
}

__device__ __forceinline__ int load_idx(const void* ei, int pos, int is64) {
    if (is64) return (int)((const long long*)ei)[pos];
    return ((const int*)ei)[pos];
}

// ---------------- reset: deg counters + agg sentinel ----------------
__global__ void __launch_bounds__(256) k_reset() {
    int i = blockIdx.x * 256 + threadIdx.x;
    if (i < NN) g_deg[i] = 0;
    if (i < NN * CC) g_agg[i] = AGG_EMPTY;
}

// ---------------- per-node transform: u, v ----------------
__global__ void __launch_bounds__(256) k_node(
    const float* __restrict__ x, const float* __restrict__ W1,
    const float* __restrict__ b1)
{
    __shared__ float W1s[64 * 129];
    __shared__ float xs[16 * 64];
    int tid = threadIdx.x + threadIdx.y * 64;
    for (int i = tid; i < 64 * 128; i += 256) {
        int c = i >> 7, k2 = i & 127;
        W1s[c * 129 + k2] = W1[i];
    }
    int node0 = blockIdx.x * 16;
    for (int i = tid; i < 16 * 64; i += 256)
        xs[i] = x[node0 * 64 + i];
    __syncthreads();

    int c = threadIdx.x;
    int g = threadIdx.y;
    float ua[4] = {0.f, 0.f, 0.f, 0.f};
    float vb[4] = {0.f, 0.f, 0.f, 0.f};
    #pragma unroll 8
    for (int k = 0; k < 64; k++) {
        float wa = W1s[c * 129 + k];
        float wb = W1s[c * 129 + 64 + k];
        #pragma unroll
        for (int j = 0; j < 4; j++) {
            float xk = xs[(g * 4 + j) * 64 + k];
            ua[j] = fmaf(xk, wa, ua[j]);
            vb[j] = fmaf(xk, wb, vb[j]);
        }
    }
    float bc = b1[c];
    #pragma unroll
    for (int j = 0; j < 4; j++) {
        int n = node0 + g * 4 + j;
        g_u[n * 64 + c] = ua[j] - vb[j] + bc;
        g_v[n * 64 + c] = vb[j];
    }
}

// ---------------- degree histogram ----------------
__global__ void __launch_bounds__(256) k_hist(const void* __restrict__ ei) {
    int e = blockIdx.x * 256 + threadIdx.x;
    int is64 = g_is64;
    if (e < NE) {
        int dst = load_idx(ei, NE + e, is64);
        if ((unsigned)dst < NN) atomicAdd(&g_deg[dst], 1);
    }
}

// ---------------- exclusive scan (single block) ----------------
__global__ void __launch_bounds__(1024) k_scan() {
    __shared__ int sums[1024];
    int t = threadIdx.x;
    int base = t * 40;
    int s = 0;
    for (int i = 0; i < 40; i++) s += g_deg[base + i];
    sums[t] = s;
    __syncthreads();
    for (int off = 1; off < 1024; off <<= 1) {
        int a = sums[t];
        int b = (t >= off) ? sums[t - off] : 0;
        __syncthreads();
        sums[t] = a + b;
        __syncthreads();
    }
    int run = (t > 0) ? sums[t - 1] : 0;
    for (int i = 0; i < 40; i++) {
        g_rowptr[base + i] = run;
        g_cursor[base + i] = run;
        run += g_deg[base + i];
    }
    if (t == 1023) g_rowptr[NN] = run;
}

// ---------------- scatter edges into CSR order ----------------
__global__ void __launch_bounds__(256) k_scatter(const void* __restrict__ ei) {
    int e = blockIdx.x * 256 + threadIdx.x;
    int is64 = g_is64;
    if (e < NE) {
        int dst = load_idx(ei, NE + e, is64);
        int src = load_idx(ei, e, is64);
        if ((unsigned)dst < NN && (unsigned)src < NN) {
            int p = atomicAdd(&g_cursor[dst], 1);
            g_ss[p] = src;
            g_sd[p] = dst;
        }
    }
}

// ---------------- helpers ----------------
__device__ __forceinline__ unsigned pack_bf2(float a, float b) {
    __nv_bfloat162 t;
    t.x = __float2bfloat16_rn(a);
    t.y = __float2bfloat16_rn(b);
    return *(unsigned*)&t;
}

__device__ __forceinline__ void flushmax(int dst, int l, float a0, float a1) {
    int b0 = __float_as_int(a0); b0 = (b0 < 0) ? (b0 ^ 0x7FFFFFFF) : b0;
    int b1 = __float_as_int(a1); b1 = (b1 < 0) ? (b1 ^ 0x7FFFFFFF) : b1;
    atomicMax(&g_agg[dst * 64 + l], b0);
    atomicMax(&g_agg[dst * 64 + 32 + l], b1);
}

#define LDSM4(r0, r1, r2, r3, addr) \
    asm volatile("ldmatrix.sync.aligned.m8n8.x4.shared.b16 {%0,%1,%2,%3}, [%4];" \
        : "=r"(r0), "=r"(r1), "=r"(r2), "=r"(r3) : "r"(addr))

#define MMA16816(acc, a0, a1, a2, a3, b0, b1) \
    asm volatile("mma.sync.aligned.m16n8k16.row.col.f32.bf16.bf16.f32 " \
        "{%0,%1,%2,%3}, {%4,%5,%6,%7}, {%8,%9}, {%0,%1,%2,%3};" \
        : "+f"((acc)[0]), "+f"((acc)[1]), "+f"((acc)[2]), "+f"((acc)[3]) \
        : "r"(a0), "r"(a1), "r"(a2), "r"(a3), "r"(b0), "r"(b1))

// ---------------- hot kernel: HMMA edge GEMM + segmented max ----------------
// Persistent blocks of 8 warps; tile = 128 consecutive CSR edges; each warp owns
// 16 rows and is fully warp-local. D[128,64] = h @ W2^T via bf16 3-split done as
// one K=192 concatenated GEMM on mma.sync (fp32 accumulate in registers).
__global__ void __launch_bounds__(256, 2) k_edge(const float* __restrict__ W2) {
    extern __shared__ __align__(16) char sm[];
    uint32_t sb = (uint32_t)__cvta_generic_to_shared(sm);

    int tid = threadIdx.x;
    int wid = tid >> 5;
    int lane = tid & 31;
    int* dstbuf = (int*)(sm + DSTOFF);
    float* Dsm = (float*)sm;   // overlays A region after MMA

    // ---- W2 split into bf16 hi/lo rows of B (once) ----
    for (int i = tid; i < 64 * 64; i += 256) {
        int n = i >> 6, k = i & 63;
        float w = W2[i];
        __nv_bfloat16 whi = __float2bfloat16_rn(w);
        float wlo = w - __bfloat162float(whi);
        *(__nv_bfloat16*)(sm + BOFF + n * ASTRIDE_B + k * 2) = whi;
        *(__nv_bfloat16*)(sm + BOFF + (64 + n) * ASTRIDE_B + k * 2) = __float2bfloat16_rn(wlo);
    }
    __syncthreads();

    // per-lane ldmatrix base addresses
    uint32_t aBase = sb + AOFF + (uint32_t)(16 * wid + (lane & 15)) * ASTRIDE_B
                   + ((lane >> 4) << 4);                      // k-half select (+16B)
    uint32_t bBase = sb + BOFF
                   + (uint32_t)((lane & 7) + ((lane >> 4) << 3)) * ASTRIDE_B  // n row
                   + (((lane >> 3) & 1) << 4);                // k-half select (+16B)

    int prow = 16 * wid + (lane >> 1);   // prep row for this thread
    int q = lane & 1;                    // prep col-half

    for (int tile = blockIdx.x; tile < NTILES; tile += gridDim.x) {
        int e0 = tile * TILE_M;
        // ---- prep: h = lrelu(u[dst] + v[src]); bf16 hi/lo into A_cat ----
        {
            int src = g_ss[e0 + prow];
            int dst = g_sd[e0 + prow];
            if (q == 0) dstbuf[prow] = dst;
            const float4* ur = (const float4*)(g_u + dst * 64 + q * 32);
            const float4* vr = (const float4*)(g_v + src * 64 + q * 32);
            char* arow = sm + AOFF + prow * ASTRIDE_B + q * 64;  // hi bytes
            #pragma unroll
            for (int j = 0; j < 8; j++) {
                float4 a = ur[j], b = vr[j];
                float h0 = a.x + b.x; h0 = fmaxf(h0, 0.01f * h0);
                float h1 = a.y + b.y; h1 = fmaxf(h1, 0.01f * h1);
                float h2 = a.z + b.z; h2 = fmaxf(h2, 0.01f * h2);
                float h3 = a.w + b.w; h3 = fmaxf(h3, 0.01f * h3);
                unsigned hiA = pack_bf2(h0, h1), hiB = pack_bf2(h2, h3);
                __nv_bfloat162 hA = *(__nv_bfloat162*)&hiA;
                __nv_bfloat162 hB = *(__nv_bfloat162*)&hiB;
                unsigned loA = pack_bf2(h0 - __bfloat162float(hA.x),
                                        h1 - __bfloat162float(hA.y));
                unsigned loB = pack_bf2(h2 - __bfloat162float(hB.x),
                                        h3 - __bfloat162float(hB.y));
                *(uint2*)(arow + j * 8)       = make_uint2(hiA, hiB);  // H_hi
                *(uint2*)(arow + 128 + j * 8) = make_uint2(loA, loB);  // H_lo
            }
        }
        __syncwarp();

        // ---- K=192 GEMM: sections (A_hi,B_hi), (A_lo,B_hi), (A_hi,B_lo) ----
        float acc[8][4];
        #pragma unroll
        for (int ni = 0; ni < 8; ni++)
            acc[ni][0] = acc[ni][1] = acc[ni][2] = acc[ni][3] = 0.0f;

        #pragma unroll
        for (int ks = 0; ks < 12; ks++) {
            int s = ks >> 2, kk = ks & 3;
            uint32_t aoff = (uint32_t)((s == 1 ? 128 : 0) + kk * 32);
            uint32_t boff = (uint32_t)((s == 2 ? 64 : 0) * ASTRIDE_B + kk * 32);
            uint32_t a0, a1, a2, a3;
            LDSM4(a0, a1, a2, a3, aBase + aoff);
            #pragma unroll
            for (int np = 0; np < 4; np++) {
                uint32_t b0, b1, b2, b3;
                LDSM4(b0, b1, b2, b3, bBase + boff + (uint32_t)(np * 16) * ASTRIDE_B);
                MMA16816(acc[2 * np],     a0, a1, a2, a3, b0, b1);
                MMA16816(acc[2 * np + 1], a0, a1, a2, a3, b2, b3);
            }
        }
        __syncwarp();   // A reads done before D staging overwrites the region

        // ---- stage D fragments to smem (warp-local rows) ----
        {
            int r0 = 16 * wid + (lane >> 2);
            int cc2 = (lane & 3) * 2;
            #pragma unroll
            for (int ni = 0; ni < 8; ni++) {
                *(float2*)(Dsm + r0 * 68 + ni * 8 + cc2) =
                    make_float2(acc[ni][0], acc[ni][1]);
                *(float2*)(Dsm + (r0 + 8) * 68 + ni * 8 + cc2) =
                    make_float2(acc[ni][2], acc[ni][3]);
            }
        }
        __syncwarp();

        // ---- segmented max over sorted dst; lane owns channels (lane, lane+32) ----
        {
            float m0 = -CUDART_INF_F, m1 = -CUDART_INF_F;
            int prevd = dstbuf[16 * wid];
            #pragma unroll 4
            for (int r = 0; r < 16; r++) {
                int row = 16 * wid + r;
                int drow = dstbuf[row];
                if (drow != prevd) {
                    flushmax(prevd, lane, m0, m1);
                    m0 = -CUDART_INF_F; m1 = -CUDART_INF_F;
                    prevd = drow;
                }
                m0 = fmaxf(m0, Dsm[row * 68 + lane]);
                m1 = fmaxf(m1, Dsm[row * 68 + 32 + lane]);
            }
            flushmax(prevd, lane, m0, m1);
        }
        __syncwarp();   // scan reads done before next tile's prep overwrites
    }
}

// ---------------- final: decode max, +b2, residual, relu ----------------
__global__ void __launch_bounds__(256) k_final(
    const float* __restrict__ x, const float* __restrict__ b2,
    float* __restrict__ out)
{
    int idx = blockIdx.x * 256 + threadIdx.x;
    if (idx >= NN * CC) return;
    int c = idx & 63;
    int k = g_agg[idx];
    float m = 0.0f;
    if (k != (int)AGG_EMPTY) {
        int b = (k < 0) ? (k ^ 0x7FFFFFFF) : k;
        m = __int_as_float(b) + b2[c];
    }
    float o = m + x[idx];
    out[idx] = fmaxf(o, 0.0f);
}

// ---------------- launch ----------------
extern "C" void kernel_launch(void* const* d_in, const int* in_sizes, int n_in,
                              void* d_out, int out_size) {
    const float* x  = (const float*)d_in[0];
    const void*  ei = d_in[1];
    const float* W1 = (const float*)d_in[2];
    const float* b1 = (const float*)d_in[3];
    const float* W2 = (const float*)d_in[4];
    const float* b2 = (const float*)d_in[5];
    float* out = (float*)d_out;

    cudaFuncSetAttribute(k_edge, cudaFuncAttributeMaxDynamicSharedMemorySize, DYNSZ);

    k_detect <<<1, 1024>>>((const int*)ei);
    k_reset  <<<(NN * CC + 255) / 256, 256>>>();
    k_node   <<<NN / 16, dim3(64, 4)>>>(x, W1, b1);
    k_hist   <<<NE / 256, 256>>>(ei);
    k_scan   <<<1, 1024>>>();
    k_scatter<<<NE / 256, 256>>>(ei);
    k_edge   <<<EDGE_GRID, 256, DYNSZ>>>(W2);
    k_final  <<<(NN * CC + 255) / 256, 256>>>(x, b2, out);
}

// round 6
// speedup vs baseline: 2.0746x; 1.1463x over previous
#include <cuda_runtime.h>
#include <cuda_fp16.h>
#include <math_constants.h>
#include <cstdint>

// Problem constants (fixed by the dataset)
#define CC    64
#define NB    2048
#define NT    20
#define NN    (NB * NT)          // 40960 nodes
#define NE    1310720            // edges
#define TILE_M 128               // edges per block tile (16 per warp)
#define NTILES (NE / TILE_M)     // 10240
#define EDGE_GRID 296            // persistent blocks (2 per SM)

// k_edge smem layout (dynamic, 16B aligned base)
#define ASTRIDE 272              // A row: 64 hi fp16 (128B) + 64 lo fp16 (128B) + 16B pad
#define BSTRIDE 144              // B row: 64 fp16 (128B) + 16B pad
#define AOFF    0                // 128 rows x 272B = 34816
#define BOFF    34816            // 64 rows x 144B = 9216
#define DSTOFF  44032            // int dst[128]
#define DYNSZ   44544
// D staging overlays A region: 128 rows x 68 fp32 (272B/row = ASTRIDE)

// k_scannode smem: scan uses first 4KB as int[1024]; node uses whole buffer
#define SN_W1OFF  0              // 64*129 floats = 33024B
#define SN_XSOFF  33024          // 64*64 floats = 16384B
#define SN_DYNSZ  49408

// -------- persistent device scratch (zero-initialized at load) --------
__device__ __align__(16) float g_u[NN * CC];   // x @ (W1a - W1b)^T + b1
__device__ __align__(16) float g_v[NN * CC];   // x @ W1b^T
__device__ int      g_deg[NN];        // zero-init; re-zeroed by k_scannode each run
__device__ int      g_rowptr[NN + 1];
__device__ int      g_cursor[NN];
__device__ int      g_ss[NE];         // edge src sorted by dst
__device__ int      g_sd[NE];         // edge dst sorted (non-decreasing)
__device__ unsigned g_agg[NN * CC];   // monotone-encoded max; 0 = empty sentinel

// monotone float->unsigned encoding: order-preserving, all finite values >= 0x00800000
__device__ __forceinline__ unsigned encf(float f) {
    unsigned b = __float_as_uint(f);
    return (b & 0x80000000u) ? ~b : (b | 0x80000000u);
}

// per-block edge_index dtype detection (int64 layout has odd 32-bit words all 0)
__device__ __forceinline__ int detect_is64(const void* ei, int* s_flag, int tid) {
    if (tid < 32) {
        int v = ((const int*)ei)[2 * tid + 1];
        unsigned m = __ballot_sync(0xFFFFFFFFu, v != 0);
        if (tid == 0) *s_flag = (m == 0u);
    }
    __syncthreads();
    return *s_flag;
}

__device__ __forceinline__ int load_idx(const void* ei, int pos, int is64) {
    if (is64) return (int)((const long long*)ei)[pos];
    return ((const int*)ei)[pos];
}

// ---------------- launch 0: degree histogram (g_deg starts zeroed) ----------------
__global__ void __launch_bounds__(256) k_hist(const void* __restrict__ ei) {
    __shared__ int s_flag;
    int tid = threadIdx.x;
    int is64 = detect_is64(ei, &s_flag, tid);
    int e = blockIdx.x * 256 + tid;
    int dst = load_idx(ei, NE + e, is64);
    if ((unsigned)dst < NN) atomicAdd(&g_deg[dst], 1);
}

// ---------------- launch 1: block 0 = exclusive scan (+re-zero deg), others = node GEMM ----------------
__global__ void __launch_bounds__(1024) k_scannode(
    const float* __restrict__ x, const float* __restrict__ W1,
    const float* __restrict__ b1)
{
    extern __shared__ __align__(16) char snsm[];
    int tid = threadIdx.x;

    if (blockIdx.x == 0) {
        // ---- exclusive scan over g_deg; build rowptr+cursor; re-zero deg ----
        int* sums = (int*)snsm;
        int base = tid * 40;
        int s = 0;
        for (int i = 0; i < 40; i++) s += g_deg[base + i];
        sums[tid] = s;
        __syncthreads();
        for (int off = 1; off < 1024; off <<= 1) {
            int a = sums[tid];
            int b = (tid >= off) ? sums[tid - off] : 0;
            __syncthreads();
            sums[tid] = a + b;
            __syncthreads();
        }
        int run = (tid > 0) ? sums[tid - 1] : 0;
        for (int i = 0; i < 40; i++) {
            g_rowptr[base + i] = run;
            g_cursor[base + i] = run;
            run += g_deg[base + i];
            g_deg[base + i] = 0;        // ready for next replay
        }
        if (tid == 1023) g_rowptr[NN] = run;
        return;
    }

    // ---- node GEMM: u = x@(W1a-W1b)^T + b1, v = x@W1b^T; 64 nodes per block ----
    float* W1s = (float*)(snsm + SN_W1OFF);   // [c][k2] padded 129
    float* xs  = (float*)(snsm + SN_XSOFF);   // [node][k]
    for (int i = tid; i < 64 * 128; i += 1024) {
        int c = i >> 7, k2 = i & 127;
        W1s[c * 129 + k2] = W1[i];
    }
    int node0 = (blockIdx.x - 1) * 64;
    for (int i = tid; i < 64 * 64; i += 1024)
        xs[i] = x[node0 * 64 + i];
    __syncthreads();

    int c = tid & 63;        // output channel
    int g = tid >> 6;        // node group (0..15), 4 nodes each
    float ua[4] = {0.f, 0.f, 0.f, 0.f};
    float vb[4] = {0.f, 0.f, 0.f, 0.f};
    #pragma unroll 8
    for (int k = 0; k < 64; k++) {
        float wa = W1s[c * 129 + k];
        float wb = W1s[c * 129 + 64 + k];
        #pragma unroll
        for (int j = 0; j < 4; j++) {
            float xk = xs[(g * 4 + j) * 64 + k];
            ua[j] = fmaf(xk, wa, ua[j]);
            vb[j] = fmaf(xk, wb, vb[j]);
        }
    }
    float bc = b1[c];
    #pragma unroll
    for (int j = 0; j < 4; j++) {
        int n = node0 + g * 4 + j;
        g_u[n * 64 + c] = ua[j] - vb[j] + bc;
        g_v[n * 64 + c] = vb[j];
    }
}

// ---------------- launch 2: scatter edges into CSR order ----------------
__global__ void __launch_bounds__(256) k_scatter(const void* __restrict__ ei) {
    __shared__ int s_flag;
    int tid = threadIdx.x;
    int is64 = detect_is64(ei, &s_flag, tid);
    int e = blockIdx.x * 256 + tid;
    int dst = load_idx(ei, NE + e, is64);
    int src = load_idx(ei, e, is64);
    if ((unsigned)dst < NN && (unsigned)src < NN) {
        int p = atomicAdd(&g_cursor[dst], 1);
        g_ss[p] = src;
        g_sd[p] = dst;
    }
}

// ---------------- helpers for k_edge ----------------
__device__ __forceinline__ unsigned pack_hf2(float a, float b) {
    __half2 t = __floats2half2_rn(a, b);
    return *(unsigned*)&t;
}

__device__ __forceinline__ void flushmax(int dst, int l, float a0, float a1) {
    atomicMax(&g_agg[dst * 64 + l], encf(a0));
    atomicMax(&g_agg[dst * 64 + 32 + l], encf(a1));
}

#define LDSM4(r0, r1, r2, r3, addr) \
    asm volatile("ldmatrix.sync.aligned.m8n8.x4.shared.b16 {%0,%1,%2,%3}, [%4];" \
        : "=r"(r0), "=r"(r1), "=r"(r2), "=r"(r3) : "r"(addr))

#define MMA16816(acc, a0, a1, a2, a3, b0, b1) \
    asm volatile("mma.sync.aligned.m16n8k16.row.col.f32.f16.f16.f32 " \
        "{%0,%1,%2,%3}, {%4,%5,%6,%7}, {%8,%9}, {%0,%1,%2,%3};" \
        : "+f"((acc)[0]), "+f"((acc)[1]), "+f"((acc)[2]), "+f"((acc)[3]) \
        : "r"(a0), "r"(a1), "r"(a2), "r"(a3), "r"(b0), "r"(b1))

// ---------------- launch 3 (PROFILED SLOT): HMMA edge GEMM + segmented max ----------------
// Persistent blocks of 8 warps; tile = 128 consecutive CSR edges; each warp owns 16 rows,
// fully warp-local. D[128,64] = h @ W2^T via fp16 2-split (A_hi*B + A_lo*B), fp32 accum.
// B (fp16 W2) fragments hoisted into registers once — zero B traffic in the loop.
__global__ void __launch_bounds__(256, 2) k_edge(const float* __restrict__ W2) {
    extern __shared__ __align__(16) char sm[];
    uint32_t sb = (uint32_t)__cvta_generic_to_shared(sm);

    int tid = threadIdx.x;
    int wid = tid >> 5;
    int lane = tid & 31;
    int* dstbuf = (int*)(sm + DSTOFF);
    float* Dsm = (float*)sm;   // overlays A region after MMA

    // ---- B = fp16(W2), [n][k] rows (col-major k x n for mma.col) ----
    for (int i = tid; i < 64 * 64; i += 256) {
        int n = i >> 6, k = i & 63;
        *(__half*)(sm + BOFF + n * BSTRIDE + k * 2) = __float2half_rn(W2[i]);
    }
    __syncthreads();

    // per-lane ldmatrix base addresses
    uint32_t aBase = sb + AOFF + (uint32_t)(16 * wid + (lane & 15)) * ASTRIDE
                   + ((lane >> 4) << 4);                        // k-half select (+16B)
    uint32_t bBase = sb + BOFF
                   + (uint32_t)((lane & 7) + ((lane >> 4) << 3)) * BSTRIDE   // n row
                   + (((lane >> 3) & 1) << 4);                  // k-half select (+16B)

    // ---- hoist all B fragments into registers (constant across tiles) ----
    uint32_t Bf[4][4][4];
    #pragma unroll
    for (int ks = 0; ks < 4; ks++)
        #pragma unroll
        for (int np = 0; np < 4; np++)
            LDSM4(Bf[ks][np][0], Bf[ks][np][1], Bf[ks][np][2], Bf[ks][np][3],
                  bBase + (uint32_t)(ks * 32) + (uint32_t)(np * 16) * BSTRIDE);
    __syncthreads();

    int prow = 16 * wid + (lane >> 1);   // prep row for this thread
    int q = lane & 1;                    // prep col-half

    for (int tile = blockIdx.x; tile < NTILES; tile += gridDim.x) {
        int e0 = tile * TILE_M;
        // ---- prep: h = lrelu(u[dst] + v[src]); fp16 hi/lo into A ----
        {
            int src = g_ss[e0 + prow];
            int dst = g_sd[e0 + prow];
            if (q == 0) dstbuf[prow] = dst;
            const float4* ur = (const float4*)(g_u + dst * 64 + q * 32);
            const float4* vr = (const float4*)(g_v + src * 64 + q * 32);
            char* arow = sm + AOFF + prow * ASTRIDE + q * 64;  // hi bytes
            #pragma unroll
            for (int j = 0; j < 8; j++) {
                float4 a = ur[j], b = vr[j];
                float h0 = a.x + b.x; h0 = fmaxf(h0, 0.01f * h0);
                float h1 = a.y + b.y; h1 = fmaxf(h1, 0.01f * h1);
                float h2 = a.z + b.z; h2 = fmaxf(h2, 0.01f * h2);
                float h3 = a.w + b.w; h3 = fmaxf(h3, 0.01f * h3);
                unsigned hiA = pack_hf2(h0, h1), hiB = pack_hf2(h2, h3);
                __half2 hA = *(__half2*)&hiA;
                __half2 hB = *(__half2*)&hiB;
                unsigned loA = pack_hf2(h0 - __half2float(hA.x),
                                        h1 - __half2float(hA.y));
                unsigned loB = pack_hf2(h2 - __half2float(hB.x),
                                        h3 - __half2float(hB.y));
                *(uint2*)(arow + j * 8)       = make_uint2(hiA, hiB);  // H_hi
                *(uint2*)(arow + 128 + j * 8) = make_uint2(loA, loB);  // H_lo
            }
        }
        __syncwarp();

        // ---- K=128 GEMM: (A_hi, B) + (A_lo, B) ----
        float acc[8][4];
        #pragma unroll
        for (int ni = 0; ni < 8; ni++)
            acc[ni][0] = acc[ni][1] = acc[ni][2] = acc[ni][3] = 0.0f;

        #pragma unroll
        for (int ks = 0; ks < 4; ks++) {
            uint32_t a0, a1, a2, a3;
            LDSM4(a0, a1, a2, a3, aBase + (uint32_t)(ks * 32));          // A_hi
            #pragma unroll
            for (int np = 0; np < 4; np++) {
                MMA16816(acc[2 * np],     a0, a1, a2, a3, Bf[ks][np][0], Bf[ks][np][1]);
                MMA16816(acc[2 * np + 1], a0, a1, a2, a3, Bf[ks][np][2], Bf[ks][np][3]);
            }
            LDSM4(a0, a1, a2, a3, aBase + (uint32_t)(128 + ks * 32));    // A_lo
            #pragma unroll
            for (int np = 0; np < 4; np++) {
                MMA16816(acc[2 * np],     a0, a1, a2, a3, Bf[ks][np][0], Bf[ks][np][1]);
                MMA16816(acc[2 * np + 1], a0, a1, a2, a3, Bf[ks][np][2], Bf[ks][np][3]);
            }
        }
        __syncwarp();   // A reads done before D staging overwrites the region

        // ---- stage D fragments to smem (warp-local rows) ----
        {
            int r0 = 16 * wid + (lane >> 2);
            int cc2 = (lane & 3) * 2;
            #pragma unroll
            for (int ni = 0; ni < 8; ni++) {
                *(float2*)(Dsm + r0 * 68 + ni * 8 + cc2) =
                    make_float2(acc[ni][0], acc[ni][1]);
                *(float2*)(Dsm + (r0 + 8) * 68 + ni * 8 + cc2) =
                    make_float2(acc[ni][2], acc[ni][3]);
            }
        }
        __syncwarp();

        // ---- segmented max over sorted dst; lane owns channels (lane, lane+32) ----
        {
            float m0 = -CUDART_INF_F, m1 = -CUDART_INF_F;
            int prevd = dstbuf[16 * wid];
            #pragma unroll 4
            for (int r = 0; r < 16; r++) {
                int row = 16 * wid + r;
                int drow = dstbuf[row];
                if (drow != prevd) {
                    flushmax(prevd, lane, m0, m1);
                    m0 = -CUDART_INF_F; m1 = -CUDART_INF_F;
                    prevd = drow;
                }
                m0 = fmaxf(m0, Dsm[row * 68 + lane]);
                m1 = fmaxf(m1, Dsm[row * 68 + 32 + lane]);
            }
            flushmax(prevd, lane, m0, m1);
        }
        __syncwarp();   // scan reads done before next tile's prep overwrites
    }
}

// ---------------- launch 4: decode max, +b2, residual, relu; reset agg ----------------
__global__ void __launch_bounds__(256) k_final(
    const float* __restrict__ x, const float* __restrict__ b2,
    float* __restrict__ out)
{
    int idx = blockIdx.x * 256 + threadIdx.x;
    int c = idx & 63;
    unsigned u = g_agg[idx];
    g_agg[idx] = 0u;                      // ready for next replay
    float m = 0.0f;
    if (u >= 0x00800000u) {               // any finite value encodes >= this
        unsigned b = (u & 0x80000000u) ? (u & 0x7FFFFFFFu) : ~u;
        m = __uint_as_float(b) + b2[c];
    }
    float o = m + x[idx];
    out[idx] = fmaxf(o, 0.0f);
}

// ---------------- launch ----------------
extern "C" void kernel_launch(void* const* d_in, const int* in_sizes, int n_in,
                              void* d_out, int out_size) {
    const float* x  = (const float*)d_in[0];
    const void*  ei = d_in[1];
    const float* W1 = (const float*)d_in[2];
    const float* b1 = (const float*)d_in[3];
    const float* W2 = (const float*)d_in[4];
    const float* b2 = (const float*)d_in[5];
    float* out = (float*)d_out;

    cudaFuncSetAttribute(k_scannode, cudaFuncAttributeMaxDynamicSharedMemorySize, SN_DYNSZ);
    cudaFuncSetAttribute(k_edge, cudaFuncAttributeMaxDynamicSharedMemorySize, DYNSZ);

    k_hist    <<<NE / 256, 256>>>(ei);
    k_scannode<<<NN / 64 + 1, 1024, SN_DYNSZ>>>(x, W1, b1);
    k_scatter <<<NE / 256, 256>>>(ei);
    k_edge    <<<EDGE_GRID, 256, DYNSZ>>>(W2);
    k_final   <<<(NN * CC) / 256, 256>>>(x, b2, out);
}

// round 7
// speedup vs baseline: 2.2665x; 1.0925x over previous
#include <cuda_runtime.h>
#include <cuda_fp16.h>
#include <math_constants.h>
#include <cstdint>

// Problem constants (fixed by the dataset)
#define CC    64
#define NB    2048
#define NT    20
#define NN    (NB * NT)          // 40960 nodes
#define NE    1310720            // edges
#define TILE_M 128               // edges per block tile (16 per warp)
#define NTILES (NE / TILE_M)     // 10240
#define EDGE_GRID 296            // persistent blocks (2 per SM)

#define BSTRIDE 144              // B row: 64 fp16 (128B) + 16B pad
#define DYNSZ   (64 * BSTRIDE)   // k_edge smem: only B

// k_scannode smem: scan uses first 4KB as int[1024]; node uses whole buffer
#define SN_W1OFF  0              // 64*129 floats = 33024B
#define SN_XSOFF  33024          // 64*64 floats = 16384B
#define SN_DYNSZ  49408

// -------- persistent device scratch (zero-initialized at load) --------
__device__ __align__(16) float g_u[NN * CC];   // x @ (W1a - W1b)^T + b1
__device__ __align__(16) float g_v[NN * CC];   // x @ W1b^T
__device__ int      g_deg[NN];        // zero-init; re-zeroed by k_scannode each run
__device__ int      g_rowptr[NN + 1];
__device__ int      g_cursor[NN];
__device__ int      g_ss[NE];         // edge src sorted by dst
__device__ int      g_sd[NE];         // edge dst sorted (non-decreasing)
__device__ unsigned g_agg[NN * CC];   // monotone-encoded max; 0 = empty sentinel

// monotone float->unsigned encoding: order-preserving, finite values >= 0x00800000
__device__ __forceinline__ unsigned encf(float f) {
    unsigned b = __float_as_uint(f);
    return (b & 0x80000000u) ? ~b : (b | 0x80000000u);
}

// per-block edge_index dtype detection (int64 layout has odd 32-bit words all 0)
__device__ __forceinline__ int detect_is64(const void* ei, int* s_flag, int tid) {
    if (tid < 32) {
        int v = ((const int*)ei)[2 * tid + 1];
        unsigned m = __ballot_sync(0xFFFFFFFFu, v != 0);
        if (tid == 0) *s_flag = (m == 0u);
    }
    __syncthreads();
    return *s_flag;
}

__device__ __forceinline__ int load_idx(const void* ei, int pos, int is64) {
    if (is64) return (int)((const long long*)ei)[pos];
    return ((const int*)ei)[pos];
}

// ---------------- launch 0: degree histogram (2 edges/thread) ----------------
__global__ void __launch_bounds__(256) k_hist(const void* __restrict__ ei) {
    __shared__ int s_flag;
    int tid = threadIdx.x;
    int is64 = detect_is64(ei, &s_flag, tid);
    int e = (blockIdx.x * 256 + tid) * 2;
    #pragma unroll
    for (int j = 0; j < 2; j++) {
        int dst = load_idx(ei, NE + e + j, is64);
        if ((unsigned)dst < NN) atomicAdd(&g_deg[dst], 1);
    }
}

// ---------------- launch 1: block 0 = scan (+re-zero deg), others = node GEMM ----------------
__global__ void __launch_bounds__(1024) k_scannode(
    const float* __restrict__ x, const float* __restrict__ W1,
    const float* __restrict__ b1)
{
    extern __shared__ __align__(16) char snsm[];
    int tid = threadIdx.x;

    if (blockIdx.x == 0) {
        int* sums = (int*)snsm;
        int base = tid * 40;
        int s = 0;
        for (int i = 0; i < 40; i++) s += g_deg[base + i];
        sums[tid] = s;
        __syncthreads();
        for (int off = 1; off < 1024; off <<= 1) {
            int a = sums[tid];
            int b = (tid >= off) ? sums[tid - off] : 0;
            __syncthreads();
            sums[tid] = a + b;
            __syncthreads();
        }
        int run = (tid > 0) ? sums[tid - 1] : 0;
        for (int i = 0; i < 40; i++) {
            g_rowptr[base + i] = run;
            g_cursor[base + i] = run;
            run += g_deg[base + i];
            g_deg[base + i] = 0;        // ready for next replay
        }
        if (tid == 1023) g_rowptr[NN] = run;
        return;
    }

    float* W1s = (float*)(snsm + SN_W1OFF);   // [c][k2] padded 129
    float* xs  = (float*)(snsm + SN_XSOFF);   // [node][k]
    for (int i = tid; i < 64 * 128; i += 1024) {
        int c = i >> 7, k2 = i & 127;
        W1s[c * 129 + k2] = W1[i];
    }
    int node0 = (blockIdx.x - 1) * 64;
    for (int i = tid; i < 64 * 64; i += 1024)
        xs[i] = x[node0 * 64 + i];
    __syncthreads();

    int c = tid & 63;
    int g = tid >> 6;
    float ua[4] = {0.f, 0.f, 0.f, 0.f};
    float vb[4] = {0.f, 0.f, 0.f, 0.f};
    #pragma unroll 8
    for (int k = 0; k < 64; k++) {
        float wa = W1s[c * 129 + k];
        float wb = W1s[c * 129 + 64 + k];
        #pragma unroll
        for (int j = 0; j < 4; j++) {
            float xk = xs[(g * 4 + j) * 64 + k];
            ua[j] = fmaf(xk, wa, ua[j]);
            vb[j] = fmaf(xk, wb, vb[j]);
        }
    }
    float bc = b1[c];
    #pragma unroll
    for (int j = 0; j < 4; j++) {
        int n = node0 + g * 4 + j;
        g_u[n * 64 + c] = ua[j] - vb[j] + bc;
        g_v[n * 64 + c] = vb[j];
    }
}

// ---------------- launch 2: scatter edges into CSR order (2 edges/thread) ----------------
__global__ void __launch_bounds__(256) k_scatter(const void* __restrict__ ei) {
    __shared__ int s_flag;
    int tid = threadIdx.x;
    int is64 = detect_is64(ei, &s_flag, tid);
    int e = (blockIdx.x * 256 + tid) * 2;
    #pragma unroll
    for (int j = 0; j < 2; j++) {
        int dst = load_idx(ei, NE + e + j, is64);
        int src = load_idx(ei, e + j, is64);
        if ((unsigned)dst < NN && (unsigned)src < NN) {
            int p = atomicAdd(&g_cursor[dst], 1);
            g_ss[p] = src;
            g_sd[p] = dst;
        }
    }
}

// ---------------- k_edge helpers ----------------
// build one fp16x2 hi/lo A-fragment pair: h = lrelu(u+v) at cols (c, c+1)
__device__ __forceinline__ void mkfrag(const float* __restrict__ u,
                                       const float* __restrict__ v,
                                       int c, unsigned& hi, unsigned& lo) {
    float2 uu = *(const float2*)(u + c);
    float2 vv = *(const float2*)(v + c);
    float h0 = uu.x + vv.x; h0 = fmaxf(h0, 0.01f * h0);
    float h1 = uu.y + vv.y; h1 = fmaxf(h1, 0.01f * h1);
    __half2 hh = __floats2half2_rn(h0, h1);
    hi = *(unsigned*)&hh;
    __half2 ll = __floats2half2_rn(h0 - __half2float(__low2half(hh)),
                                   h1 - __half2float(__high2half(hh)));
    lo = *(unsigned*)&ll;
}

#define LDSM4(r0, r1, r2, r3, addr) \
    asm volatile("ldmatrix.sync.aligned.m8n8.x4.shared.b16 {%0,%1,%2,%3}, [%4];" \
        : "=r"(r0), "=r"(r1), "=r"(r2), "=r"(r3) : "r"(addr))

#define MMA16816(acc, a0, a1, a2, a3, b0, b1) \
    asm volatile("mma.sync.aligned.m16n8k16.row.col.f32.f16.f16.f32 " \
        "{%0,%1,%2,%3}, {%4,%5,%6,%7}, {%8,%9}, {%0,%1,%2,%3};" \
        : "+f"((acc)[0]), "+f"((acc)[1]), "+f"((acc)[2]), "+f"((acc)[3]) \
        : "r"(a0), "r"(a1), "r"(a2), "r"(a3), "r"(b0), "r"(b1))

// ---------------- launch 3: HMMA edge GEMM, register-direct, shuffle seg-max ----------------
// Persistent blocks of 8 independent warps; warp-tile = 16 consecutive CSR edges.
// A fragments (fp16 hi/lo 2-split of h) computed directly in registers from u/v gathers.
// B (fp16 W2) fragments hoisted into registers. Segmented max via xor-shuffle over the
// 8 lanes that share (lane&3); flush via 2 atomicMax per lane per run.
__global__ void __launch_bounds__(256, 2) k_edge(const float* __restrict__ W2) {
    extern __shared__ __align__(16) char sm[];
    uint32_t sb = (uint32_t)__cvta_generic_to_shared(sm);
    int tid = threadIdx.x;
    int wid = tid >> 5;
    int lane = tid & 31;

    // ---- B = fp16(W2), [n][k] rows (col-major kxn for mma .col) ----
    for (int i = tid; i < 64 * 64; i += 256) {
        int n = i >> 6, k = i & 63;
        *(__half*)(sm + n * BSTRIDE + k * 2) = __float2half_rn(W2[i]);
    }
    __syncthreads();
    uint32_t bBase = sb + (uint32_t)((lane & 7) + ((lane >> 4) << 3)) * BSTRIDE
                   + (((lane >> 3) & 1) << 4);
    uint32_t Bf[4][4][4];
    #pragma unroll
    for (int ks = 0; ks < 4; ks++)
        #pragma unroll
        for (int np = 0; np < 4; np++)
            LDSM4(Bf[ks][np][0], Bf[ks][np][1], Bf[ks][np][2], Bf[ks][np][3],
                  bBase + (uint32_t)(ks * 32) + (uint32_t)(np * 16) * BSTRIDE);
    // B smem never written again; no further block syncs needed.

    int rq = lane >> 2;          // fragment row within warp-tile (0..7; +8 pair)
    int q2 = (lane & 3) * 2;     // fragment col pair base

    for (int tile = blockIdx.x; tile < NTILES; tile += gridDim.x) {
        int e0 = tile * TILE_M + wid * 16;
        int rowA = e0 + rq, rowB = rowA + 8;
        const float* uA = g_u + g_sd[rowA] * 64;
        const float* vA = g_v + g_ss[rowA] * 64;
        const float* uB = g_u + g_sd[rowB] * 64;
        const float* vB = g_v + g_ss[rowB] * 64;

        float acc[8][4];
        #pragma unroll
        for (int ni = 0; ni < 8; ni++)
            acc[ni][0] = acc[ni][1] = acc[ni][2] = acc[ni][3] = 0.0f;

        #pragma unroll
        for (int ks = 0; ks < 4; ks++) {
            int c0 = ks * 16 + q2;
            int c1 = c0 + 8;
            unsigned a0h, a0l, a1h, a1l, a2h, a2l, a3h, a3l;
            mkfrag(uA, vA, c0, a0h, a0l);   // (rowA, k-lo)
            mkfrag(uB, vB, c0, a1h, a1l);   // (rowB, k-lo)
            mkfrag(uA, vA, c1, a2h, a2l);   // (rowA, k-hi)
            mkfrag(uB, vB, c1, a3h, a3l);   // (rowB, k-hi)
            #pragma unroll
            for (int np = 0; np < 4; np++) {
                MMA16816(acc[2 * np],     a0h, a1h, a2h, a3h, Bf[ks][np][0], Bf[ks][np][1]);
                MMA16816(acc[2 * np + 1], a0h, a1h, a2h, a3h, Bf[ks][np][2], Bf[ks][np][3]);
            }
            #pragma unroll
            for (int np = 0; np < 4; np++) {
                MMA16816(acc[2 * np],     a0l, a1l, a2l, a3l, Bf[ks][np][0], Bf[ks][np][1]);
                MMA16816(acc[2 * np + 1], a0l, a1l, a2l, a3l, Bf[ks][np][2], Bf[ks][np][3]);
            }
        }

        // ---- segmented max over sorted dst (runs within this warp's 16 rows) ----
        int myrow = lane & 15;
        int dmy = g_sd[tile * TILE_M + wid * 16 + myrow];
        int dprev = __shfl_up_sync(0xFFFFFFFFu, dmy, 1);
        unsigned mask = __ballot_sync(0xFFFFFFFFu,
                            (lane < 16) && (lane == 0 || dmy != dprev)) & 0xFFFFu;
        int a = 0;
        while (a < 16) {
            unsigned rest = mask & ~((1u << (a + 1)) - 1u);
            int b = rest ? (__ffs(rest) - 1) : 16;
            int dseg = __shfl_sync(0xFFFFFFFFu, dmy, a);
            bool in0 = (rq >= a) && (rq < b);
            bool in1 = (rq + 8 >= a) && (rq + 8 < b);
            #pragma unroll
            for (int ni = 0; ni < 8; ni++) {
                float m0 = fmaxf(in0 ? acc[ni][0] : -CUDART_INF_F,
                                 in1 ? acc[ni][2] : -CUDART_INF_F);
                float m1 = fmaxf(in0 ? acc[ni][1] : -CUDART_INF_F,
                                 in1 ? acc[ni][3] : -CUDART_INF_F);
                #pragma unroll
                for (int off = 4; off <= 16; off <<= 1) {
                    m0 = fmaxf(m0, __shfl_xor_sync(0xFFFFFFFFu, m0, off));
                    m1 = fmaxf(m1, __shfl_xor_sync(0xFFFFFFFFu, m1, off));
                }
                if (rq == ni) {   // this lane group flushes n-tile ni
                    atomicMax(&g_agg[dseg * 64 + ni * 8 + q2],     encf(m0));
                    atomicMax(&g_agg[dseg * 64 + ni * 8 + q2 + 1], encf(m1));
                }
            }
            a = b;
        }
    }
}

// ---------------- launch 4: decode max, +b2, residual, relu; reset agg ----------------
__global__ void __launch_bounds__(256) k_final(
    const float* __restrict__ x, const float* __restrict__ b2,
    float* __restrict__ out)
{
    int idx = blockIdx.x * 256 + threadIdx.x;
    int c = idx & 63;
    unsigned u = g_agg[idx];
    g_agg[idx] = 0u;                      // ready for next replay
    float m = 0.0f;
    if (u >= 0x00800000u) {               // any finite value encodes >= this
        unsigned b = (u & 0x80000000u) ? (u & 0x7FFFFFFFu) : ~u;
        m = __uint_as_float(b) + b2[c];
    }
    float o = m + x[idx];
    out[idx] = fmaxf(o, 0.0f);
}

// ---------------- launch ----------------
extern "C" void kernel_launch(void* const* d_in, const int* in_sizes, int n_in,
                              void* d_out, int out_size) {
    const float* x  = (const float*)d_in[0];
    const void*  ei = d_in[1];
    const float* W1 = (const float*)d_in[2];
    const float* b1 = (const float*)d_in[3];
    const float* W2 = (const float*)d_in[4];
    const float* b2 = (const float*)d_in[5];
    float* out = (float*)d_out;

    cudaFuncSetAttribute(k_scannode, cudaFuncAttributeMaxDynamicSharedMemorySize, SN_DYNSZ);
    cudaFuncSetAttribute(k_edge, cudaFuncAttributeMaxDynamicSharedMemorySize, DYNSZ);

    k_hist    <<<NE / 512, 256>>>(ei);
    k_scannode<<<NN / 64 + 1, 1024, SN_DYNSZ>>>(x, W1, b1);
    k_scatter <<<NE / 512, 256>>>(ei);
    k_edge    <<<EDGE_GRID, 256, DYNSZ>>>(W2);
    k_final   <<<(NN * CC) / 256, 256>>>(x, b2, out);
}

// round 8
// speedup vs baseline: 2.2812x; 1.0065x over previous
#include <cuda_runtime.h>
#include <cuda_fp16.h>
#include <math_constants.h>
#include <cstdint>

// Problem constants (fixed by the dataset)
#define CC    64
#define NB    2048
#define NT    20
#define NN    (NB * NT)          // 40960 nodes
#define NE    1310720            // edges
#define TILE_M 128               // edges per block tile (16 per warp)
#define NTILES (NE / TILE_M)     // 10240
#define EDGE_GRID 296            // persistent blocks (2 per SM)

// k_edge smem: per-warp A tiles + shared B
// A row layout (256B data, 272B stride): [h0 hi 64B][h0 lo 64B][h1 hi 64B][h1 lo 64B]
#define ASTR    272
#define AWARP   (16 * ASTR)      // 4352 per warp
#define BOFF    (8 * AWARP)      // 34816
#define BSTRIDE 144              // B row: 64 fp16 + pad
#define DYNSZ   (BOFF + 64 * BSTRIDE)   // 44032

// k_scannode smem
#define SN_W1OFF  0                       // float2 W1p[64][65] = 33280B
#define SN_XTOFF  33280                   // float xs_t[64][68] = 17408B
#define SN_DYNSZ  (33280 + 17408)         // 50688

// -------- persistent device scratch (zero-initialized at load) --------
__device__ __align__(16) float g_u[NN * CC];   // x @ (W1a - W1b)^T + b1
__device__ __align__(16) float g_v[NN * CC];   // x @ W1b^T
__device__ int      g_deg[NN];        // zero-init; re-zeroed by k_scannode each run
__device__ int      g_rowptr[NN + 1];
__device__ int      g_cursor[NN];
__device__ int      g_ss[NE];         // edge src sorted by dst
__device__ int      g_sd[NE];         // edge dst sorted (non-decreasing)
__device__ unsigned g_agg[NN * CC];   // monotone-encoded max; 0 = empty sentinel

// monotone float->unsigned encoding: order-preserving, finite values >= 0x00800000
__device__ __forceinline__ unsigned encf(float f) {
    unsigned b = __float_as_uint(f);
    return (b & 0x80000000u) ? ~b : (b | 0x80000000u);
}

// per-block edge_index dtype detection (int64 layout has odd 32-bit words all 0)
__device__ __forceinline__ int detect_is64(const void* ei, int* s_flag, int tid) {
    if (tid < 32) {
        int v = ((const int*)ei)[2 * tid + 1];
        unsigned m = __ballot_sync(0xFFFFFFFFu, v != 0);
        if (tid == 0) *s_flag = (m == 0u);
    }
    __syncthreads();
    return *s_flag;
}

__device__ __forceinline__ int load_idx(const void* ei, int pos, int is64) {
    if (is64) return (int)((const long long*)ei)[pos];
    return ((const int*)ei)[pos];
}

// ---------------- launch 0: degree histogram (2 edges/thread) ----------------
__global__ void __launch_bounds__(256) k_hist(const void* __restrict__ ei) {
    __shared__ int s_flag;
    int tid = threadIdx.x;
    int is64 = detect_is64(ei, &s_flag, tid);
    int e = (blockIdx.x * 256 + tid) * 2;
    #pragma unroll
    for (int j = 0; j < 2; j++) {
        int dst = load_idx(ei, NE + e + j, is64);
        if ((unsigned)dst < NN) atomicAdd(&g_deg[dst], 1);
    }
}

// ---------------- launch 1: block 0 = scan (+re-zero deg), others = node GEMM ----------------
__global__ void __launch_bounds__(1024) k_scannode(
    const float* __restrict__ x, const float* __restrict__ W1,
    const float* __restrict__ b1)
{
    extern __shared__ __align__(16) char snsm[];
    int tid = threadIdx.x;

    if (blockIdx.x == 0) {
        int* sums = (int*)snsm;
        int base = tid * 40;
        int s = 0;
        for (int i = 0; i < 40; i++) s += g_deg[base + i];
        sums[tid] = s;
        __syncthreads();
        for (int off = 1; off < 1024; off <<= 1) {
            int a = sums[tid];
            int b = (tid >= off) ? sums[tid - off] : 0;
            __syncthreads();
            sums[tid] = a + b;
            __syncthreads();
        }
        int run = (tid > 0) ? sums[tid - 1] : 0;
        for (int i = 0; i < 40; i++) {
            g_rowptr[base + i] = run;
            g_cursor[base + i] = run;
            run += g_deg[base + i];
            g_deg[base + i] = 0;        // ready for next replay
        }
        if (tid == 1023) g_rowptr[NN] = run;
        return;
    }

    // W1p[c][k] = (W1[c][k], W1[c][64+k]) as float2, row stride 65
    float2* W1p = (float2*)(snsm + SN_W1OFF);
    // xs_t[k][n] transposed x tile, row stride 68 floats (16B-aligned rows)
    float* xs_t = (float*)(snsm + SN_XTOFF);
    for (int i = tid; i < 64 * 64; i += 1024) {
        int c = i >> 6, k = i & 63;
        W1p[c * 65 + k] = make_float2(W1[c * 128 + k], W1[c * 128 + 64 + k]);
    }
    int node0 = (blockIdx.x - 1) * 64;
    for (int i = tid; i < 64 * 64; i += 1024) {
        int n = i >> 6, k = i & 63;
        xs_t[k * 68 + n] = x[node0 * 64 + i];
    }
    __syncthreads();

    int c = tid & 63;
    int g = tid >> 6;
    float ua[4] = {0.f, 0.f, 0.f, 0.f};
    float vb[4] = {0.f, 0.f, 0.f, 0.f};
    #pragma unroll 8
    for (int k = 0; k < 64; k++) {
        float2 w = W1p[c * 65 + k];
        float4 xv = *(const float4*)(xs_t + k * 68 + g * 4);
        ua[0] = fmaf(xv.x, w.x, ua[0]); vb[0] = fmaf(xv.x, w.y, vb[0]);
        ua[1] = fmaf(xv.y, w.x, ua[1]); vb[1] = fmaf(xv.y, w.y, vb[1]);
        ua[2] = fmaf(xv.z, w.x, ua[2]); vb[2] = fmaf(xv.z, w.y, vb[2]);
        ua[3] = fmaf(xv.w, w.x, ua[3]); vb[3] = fmaf(xv.w, w.y, vb[3]);
    }
    float bc = b1[c];
    #pragma unroll
    for (int j = 0; j < 4; j++) {
        int n = node0 + g * 4 + j;
        g_u[n * 64 + c] = ua[j] - vb[j] + bc;
        g_v[n * 64 + c] = vb[j];
    }
}

// ---------------- launch 2: scatter edges into CSR order (2 edges/thread) ----------------
__global__ void __launch_bounds__(256) k_scatter(const void* __restrict__ ei) {
    __shared__ int s_flag;
    int tid = threadIdx.x;
    int is64 = detect_is64(ei, &s_flag, tid);
    int e = (blockIdx.x * 256 + tid) * 2;
    #pragma unroll
    for (int j = 0; j < 2; j++) {
        int dst = load_idx(ei, NE + e + j, is64);
        int src = load_idx(ei, e + j, is64);
        if ((unsigned)dst < NN && (unsigned)src < NN) {
            int p = atomicAdd(&g_cursor[dst], 1);
            g_ss[p] = src;
            g_sd[p] = dst;
        }
    }
}

#define LDSM4(r0, r1, r2, r3, addr) \
    asm volatile("ldmatrix.sync.aligned.m8n8.x4.shared.b16 {%0,%1,%2,%3}, [%4];" \
        : "=r"(r0), "=r"(r1), "=r"(r2), "=r"(r3) : "r"(addr))

#define MMA16816(acc, a0, a1, a2, a3, b0, b1) \
    asm volatile("mma.sync.aligned.m16n8k16.row.col.f32.f16.f16.f32 " \
        "{%0,%1,%2,%3}, {%4,%5,%6,%7}, {%8,%9}, {%0,%1,%2,%3};" \
        : "+f"((acc)[0]), "+f"((acc)[1]), "+f"((acc)[2]), "+f"((acc)[3]) \
        : "r"(a0), "r"(a1), "r"(a2), "r"(a3), "r"(b0), "r"(b1))

// ---------------- launch 3: HMMA edge GEMM, coalesced prep, shuffle seg-max ----------------
// Persistent blocks of 8 independent warps; warp-tile = 16 consecutive CSR edges.
// Prep: coalesced LDG.128 of u/v (4 rows x 128B per instr), h = lrelu(u+v), fp16 hi/lo
// 2-split stored to per-warp smem A tile; 8 LDSM4 feed 64 HMMA. Segmented max via
// xor-shuffle; flush via atomicMax per dst-run.
__global__ void __launch_bounds__(256, 2) k_edge(const float* __restrict__ W2) {
    extern __shared__ __align__(16) char sm[];
    uint32_t sb = (uint32_t)__cvta_generic_to_shared(sm);
    int tid = threadIdx.x;
    int wid = tid >> 5;
    int lane = tid & 31;

    // ---- B = fp16(W2), [n][k] rows (col-major kxn for mma .col) ----
    for (int i = tid; i < 64 * 64; i += 256) {
        int n = i >> 6, k = i & 63;
        *(__half*)(sm + BOFF + n * BSTRIDE + k * 2) = __float2half_rn(W2[i]);
    }
    __syncthreads();
    uint32_t bBase = sb + BOFF + (uint32_t)((lane & 7) + ((lane >> 4) << 3)) * BSTRIDE
                   + (((lane >> 3) & 1) << 4);
    uint32_t Bf[4][4][4];
    #pragma unroll
    for (int ks = 0; ks < 4; ks++)
        #pragma unroll
        for (int np = 0; np < 4; np++)
            LDSM4(Bf[ks][np][0], Bf[ks][np][1], Bf[ks][np][2], Bf[ks][np][3],
                  bBase + (uint32_t)(ks * 32) + (uint32_t)(np * 16) * BSTRIDE);
    // B smem never written again; no further block syncs needed.

    char* aw = sm + wid * AWARP;                      // this warp's A tile
    // LDSM lane address pieces: row = lane&15, +16B for lanes 16-31
    uint32_t aLane = sb + (uint32_t)(wid * AWARP)
                   + (uint32_t)(lane & 15) * ASTR + (((uint32_t)lane >> 4) << 4);
    int rq = lane >> 2;          // fragment row (0..7; +8 pair)
    int q2 = (lane & 3) * 2;     // fragment col pair base
    int pr = lane >> 3;          // prep row-within-group (0..3)
    int pc = lane & 7;           // prep col block (0..7)

    for (int tile = blockIdx.x; tile < NTILES; tile += gridDim.x) {
        int e0 = tile * TILE_M + wid * 16;
        // row indices for this warp's 16 edges (lanes 0-15; others mirror)
        int dmy = g_sd[e0 + (lane & 15)];
        int smy = g_ss[e0 + (lane & 15)];

        // ---- prep: coalesced gather u/v, compute h, fp16 hi/lo split, STS ----
        #pragma unroll
        for (int it = 0; it < 4; it++) {
            int r = 4 * it + pr;
            int dn = __shfl_sync(0xFFFFFFFFu, dmy, r);
            int sn = __shfl_sync(0xFFFFFFFFu, smy, r);
            const float4* up = (const float4*)(g_u + dn * 64);
            const float4* vp = (const float4*)(g_v + sn * 64);
            char* rowp = aw + r * ASTR;
            #pragma unroll
            for (int h = 0; h < 2; h++) {
                float4 a = up[h * 8 + pc];
                float4 b = vp[h * 8 + pc];
                float h0 = a.x + b.x; h0 = fmaxf(h0, 0.01f * h0);
                float h1 = a.y + b.y; h1 = fmaxf(h1, 0.01f * h1);
                float h2 = a.z + b.z; h2 = fmaxf(h2, 0.01f * h2);
                float h3 = a.w + b.w; h3 = fmaxf(h3, 0.01f * h3);
                __half2 hiA = __floats2half2_rn(h0, h1);
                __half2 hiB = __floats2half2_rn(h2, h3);
                __half2 loA = __floats2half2_rn(h0 - __half2float(__low2half(hiA)),
                                                h1 - __half2float(__high2half(hiA)));
                __half2 loB = __floats2half2_rn(h2 - __half2float(__low2half(hiB)),
                                                h3 - __half2float(__high2half(hiB)));
                char* hb = rowp + h * 128;
                *(uint2*)(hb + pc * 8)      = make_uint2(*(unsigned*)&hiA, *(unsigned*)&hiB);
                *(uint2*)(hb + 64 + pc * 8) = make_uint2(*(unsigned*)&loA, *(unsigned*)&loB);
            }
        }
        __syncwarp();

        // ---- K=128 GEMM: (A_hi, B) + (A_lo, B) per 16-k step ----
        float acc[8][4];
        #pragma unroll
        for (int ni = 0; ni < 8; ni++)
            acc[ni][0] = acc[ni][1] = acc[ni][2] = acc[ni][3] = 0.0f;

        #pragma unroll
        for (int ks = 0; ks < 4; ks++) {
            uint32_t base = aLane + (uint32_t)((ks >> 1) * 128 + (ks & 1) * 32);
            uint32_t a0, a1, a2, a3;
            LDSM4(a0, a1, a2, a3, base);            // A_hi
            #pragma unroll
            for (int np = 0; np < 4; np++) {
                MMA16816(acc[2 * np],     a0, a1, a2, a3, Bf[ks][np][0], Bf[ks][np][1]);
                MMA16816(acc[2 * np + 1], a0, a1, a2, a3, Bf[ks][np][2], Bf[ks][np][3]);
            }
            LDSM4(a0, a1, a2, a3, base + 64);       // A_lo
            #pragma unroll
            for (int np = 0; np < 4; np++) {
                MMA16816(acc[2 * np],     a0, a1, a2, a3, Bf[ks][np][0], Bf[ks][np][1]);
                MMA16816(acc[2 * np + 1], a0, a1, a2, a3, Bf[ks][np][2], Bf[ks][np][3]);
            }
        }

        // ---- segmented max over sorted dst (runs within this warp's 16 rows) ----
        int dprev = __shfl_up_sync(0xFFFFFFFFu, dmy, 1);
        unsigned mask = __ballot_sync(0xFFFFFFFFu,
                            (lane < 16) && (lane == 0 || dmy != dprev)) & 0xFFFFu;
        int a = 0;
        while (a < 16) {
            unsigned rest = mask & ~((1u << (a + 1)) - 1u);
            int b = rest ? (__ffs(rest) - 1) : 16;
            int dseg = __shfl_sync(0xFFFFFFFFu, dmy, a);
            bool in0 = (rq >= a) && (rq < b);
            bool in1 = (rq + 8 >= a) && (rq + 8 < b);
            #pragma unroll
            for (int ni = 0; ni < 8; ni++) {
                float m0 = fmaxf(in0 ? acc[ni][0] : -CUDART_INF_F,
                                 in1 ? acc[ni][2] : -CUDART_INF_F);
                float m1 = fmaxf(in0 ? acc[ni][1] : -CUDART_INF_F,
                                 in1 ? acc[ni][3] : -CUDART_INF_F);
                #pragma unroll
                for (int off = 4; off <= 16; off <<= 1) {
                    m0 = fmaxf(m0, __shfl_xor_sync(0xFFFFFFFFu, m0, off));
                    m1 = fmaxf(m1, __shfl_xor_sync(0xFFFFFFFFu, m1, off));
                }
                if (rq == ni) {
                    atomicMax(&g_agg[dseg * 64 + ni * 8 + q2],     encf(m0));
                    atomicMax(&g_agg[dseg * 64 + ni * 8 + q2 + 1], encf(m1));
                }
            }
            a = b;
        }
        __syncwarp();
    }
}

// ---------------- launch 4: decode max, +b2, residual, relu; reset agg (x4 vec) ----------------
__global__ void __launch_bounds__(256) k_final(
    const float* __restrict__ x, const float* __restrict__ b2,
    float* __restrict__ out)
{
    int i4 = blockIdx.x * 256 + threadIdx.x;   // index of a 4-element group
    int c0 = (i4 * 4) & 63;
    uint4 u = *(const uint4*)(g_agg + i4 * 4);
    *(uint4*)(g_agg + i4 * 4) = make_uint4(0u, 0u, 0u, 0u);   // ready for next replay
    float4 xv = *(const float4*)(x + i4 * 4);
    float4 bv = *(const float4*)(b2 + c0);
    float4 o;
    {
        unsigned e;
        float m;
        e = u.x; m = (e >= 0x00800000u)
            ? __uint_as_float((e & 0x80000000u) ? (e & 0x7FFFFFFFu) : ~e) + bv.x : 0.0f;
        o.x = fmaxf(m + xv.x, 0.0f);
        e = u.y; m = (e >= 0x00800000u)
            ? __uint_as_float((e & 0x80000000u) ? (e & 0x7FFFFFFFu) : ~e) + bv.y : 0.0f;
        o.y = fmaxf(m + xv.y, 0.0f);
        e = u.z; m = (e >= 0x00800000u)
            ? __uint_as_float((e & 0x80000000u) ? (e & 0x7FFFFFFFu) : ~e) + bv.z : 0.0f;
        o.z = fmaxf(m + xv.z, 0.0f);
        e = u.w; m = (e >= 0x00800000u)
            ? __uint_as_float((e & 0x80000000u) ? (e & 0x7FFFFFFFu) : ~e) + bv.w : 0.0f;
        o.w = fmaxf(m + xv.w, 0.0f);
    }
    *(float4*)(out + i4 * 4) = o;
}

// ---------------- launch ----------------
extern "C" void kernel_launch(void* const* d_in, const int* in_sizes, int n_in,
                              void* d_out, int out_size) {
    const float* x  = (const float*)d_in[0];
    const void*  ei = d_in[1];
    const float* W1 = (const float*)d_in[2];
    const float* b1 = (const float*)d_in[3];
    const float* W2 = (const float*)d_in[4];
    const float* b2 = (const float*)d_in[5];
    float* out = (float*)d_out;

    cudaFuncSetAttribute(k_scannode, cudaFuncAttributeMaxDynamicSharedMemorySize, SN_DYNSZ);
    cudaFuncSetAttribute(k_edge, cudaFuncAttributeMaxDynamicSharedMemorySize, DYNSZ);

    k_hist    <<<NE / 512, 256>>>(ei);
    k_scannode<<<NN / 64 + 1, 1024, SN_DYNSZ>>>(x, W1, b1);
    k_scatter <<<NE / 512, 256>>>(ei);
    k_edge    <<<EDGE_GRID, 256, DYNSZ>>>(W2);
    k_final   <<<(NN * CC) / 1024, 256>>>(x, b2, out);
}

// round 9
// speedup vs baseline: 2.4543x; 1.0759x over previous
#include <cuda_runtime.h>
#include <cuda_fp16.h>
#include <math_constants.h>
#include <cstdint>

// Problem constants (fixed by the dataset)
#define CC    64
#define NB    2048
#define NT    20
#define NN    (NB * NT)          // 40960 nodes
#define NE    1310720            // edges
#define TILE_M 128               // edges per block tile (16 per warp)
#define NTILES (NE / TILE_M)     // 10240
#define EDGE_GRID 592            // persistent blocks (4 per SM)

// k_edge smem: per-warp A tiles + shared B (all fp16 single precision-split-free)
#define ASTR    144              // A row: 64 fp16 (128B) + 16B pad
#define AWARP   (16 * ASTR)      // 2304 per warp
#define BOFF    (8 * AWARP)      // 18432
#define BSTRIDE 144              // B row: 64 fp16 + pad
#define DYNSZ   (BOFF + 64 * BSTRIDE)   // 27648

// k_scannode smem
#define SN_W1OFF  0                       // float2 W1p[64][65] = 33280B
#define SN_XTOFF  33280                   // float xs_t[64][68] = 17408B
#define SN_DYNSZ  (33280 + 17408)         // 50688

// -------- persistent device scratch (zero-initialized at load) --------
__device__ __align__(16) float g_u[NN * CC];   // x @ (W1a - W1b)^T + b1
__device__ __align__(16) float g_v[NN * CC];   // x @ W1b^T
__device__ int      g_deg[NN];        // zero-init; re-zeroed by k_scannode each run
__device__ int      g_rowptr[NN + 1];
__device__ int      g_cursor[NN];
__device__ int      g_ss[NE];         // edge src sorted by dst
__device__ int      g_sd[NE];         // edge dst sorted (non-decreasing)
__device__ unsigned g_agg[NN * CC];   // monotone-encoded max; 0 = empty sentinel

// monotone float->unsigned encoding: order-preserving, finite values >= 0x00800000
__device__ __forceinline__ unsigned encf(float f) {
    unsigned b = __float_as_uint(f);
    return (b & 0x80000000u) ? ~b : (b | 0x80000000u);
}

// per-block edge_index dtype detection (int64 layout has odd 32-bit words all 0)
__device__ __forceinline__ int detect_is64(const void* ei, int* s_flag, int tid) {
    if (tid < 32) {
        int v = ((const int*)ei)[2 * tid + 1];
        unsigned m = __ballot_sync(0xFFFFFFFFu, v != 0);
        if (tid == 0) *s_flag = (m == 0u);
    }
    __syncthreads();
    return *s_flag;
}

__device__ __forceinline__ int load_idx(const void* ei, int pos, int is64) {
    if (is64) return (int)((const long long*)ei)[pos];
    return ((const int*)ei)[pos];
}

// ---------------- launch 0: degree histogram (2 edges/thread) ----------------
__global__ void __launch_bounds__(256) k_hist(const void* __restrict__ ei) {
    __shared__ int s_flag;
    int tid = threadIdx.x;
    int is64 = detect_is64(ei, &s_flag, tid);
    int e = (blockIdx.x * 256 + tid) * 2;
    #pragma unroll
    for (int j = 0; j < 2; j++) {
        int dst = load_idx(ei, NE + e + j, is64);
        if ((unsigned)dst < NN) atomicAdd(&g_deg[dst], 1);
    }
}

// ---------------- launch 1: block 0 = scan (+re-zero deg), others = node GEMM ----------------
__global__ void __launch_bounds__(1024) k_scannode(
    const float* __restrict__ x, const float* __restrict__ W1,
    const float* __restrict__ b1)
{
    extern __shared__ __align__(16) char snsm[];
    int tid = threadIdx.x;

    if (blockIdx.x == 0) {
        int* sums = (int*)snsm;
        int base = tid * 40;
        int s = 0;
        for (int i = 0; i < 40; i++) s += g_deg[base + i];
        sums[tid] = s;
        __syncthreads();
        for (int off = 1; off < 1024; off <<= 1) {
            int a = sums[tid];
            int b = (tid >= off) ? sums[tid - off] : 0;
            __syncthreads();
            sums[tid] = a + b;
            __syncthreads();
        }
        int run = (tid > 0) ? sums[tid - 1] : 0;
        for (int i = 0; i < 40; i++) {
            g_rowptr[base + i] = run;
            g_cursor[base + i] = run;
            run += g_deg[base + i];
            g_deg[base + i] = 0;        // ready for next replay
        }
        if (tid == 1023) g_rowptr[NN] = run;
        return;
    }

    float2* W1p = (float2*)(snsm + SN_W1OFF);   // (W1a, W1b) pairs, stride 65
    float* xs_t = (float*)(snsm + SN_XTOFF);    // x transposed [k][n], stride 68
    for (int i = tid; i < 64 * 64; i += 1024) {
        int c = i >> 6, k = i & 63;
        W1p[c * 65 + k] = make_float2(W1[c * 128 + k], W1[c * 128 + 64 + k]);
    }
    int node0 = (blockIdx.x - 1) * 64;
    for (int i = tid; i < 64 * 64; i += 1024) {
        int n = i >> 6, k = i & 63;
        xs_t[k * 68 + n] = x[node0 * 64 + i];
    }
    __syncthreads();

    int c = tid & 63;
    int g = tid >> 6;
    float ua[4] = {0.f, 0.f, 0.f, 0.f};
    float vb[4] = {0.f, 0.f, 0.f, 0.f};
    #pragma unroll 8
    for (int k = 0; k < 64; k++) {
        float2 w = W1p[c * 65 + k];
        float4 xv = *(const float4*)(xs_t + k * 68 + g * 4);
        ua[0] = fmaf(xv.x, w.x, ua[0]); vb[0] = fmaf(xv.x, w.y, vb[0]);
        ua[1] = fmaf(xv.y, w.x, ua[1]); vb[1] = fmaf(xv.y, w.y, vb[1]);
        ua[2] = fmaf(xv.z, w.x, ua[2]); vb[2] = fmaf(xv.z, w.y, vb[2]);
        ua[3] = fmaf(xv.w, w.x, ua[3]); vb[3] = fmaf(xv.w, w.y, vb[3]);
    }
    float bc = b1[c];
    #pragma unroll
    for (int j = 0; j < 4; j++) {
        int n = node0 + g * 4 + j;
        g_u[n * 64 + c] = ua[j] - vb[j] + bc;
        g_v[n * 64 + c] = vb[j];
    }
}

// ---------------- launch 2: scatter edges into CSR order (2 edges/thread) ----------------
__global__ void __launch_bounds__(256) k_scatter(const void* __restrict__ ei) {
    __shared__ int s_flag;
    int tid = threadIdx.x;
    int is64 = detect_is64(ei, &s_flag, tid);
    int e = (blockIdx.x * 256 + tid) * 2;
    #pragma unroll
    for (int j = 0; j < 2; j++) {
        int dst = load_idx(ei, NE + e + j, is64);
        int src = load_idx(ei, e + j, is64);
        if ((unsigned)dst < NN && (unsigned)src < NN) {
            int p = atomicAdd(&g_cursor[dst], 1);
            g_ss[p] = src;
            g_sd[p] = dst;
        }
    }
}

#define LDSM4(r0, r1, r2, r3, addr) \
    asm volatile("ldmatrix.sync.aligned.m8n8.x4.shared.b16 {%0,%1,%2,%3}, [%4];" \
        : "=r"(r0), "=r"(r1), "=r"(r2), "=r"(r3) : "r"(addr))

#define MMA16816(acc, a0, a1, a2, a3, b0, b1) \
    asm volatile("mma.sync.aligned.m16n8k16.row.col.f32.f16.f16.f32 " \
        "{%0,%1,%2,%3}, {%4,%5,%6,%7}, {%8,%9}, {%0,%1,%2,%3};" \
        : "+f"((acc)[0]), "+f"((acc)[1]), "+f"((acc)[2]), "+f"((acc)[3]) \
        : "r"(a0), "r"(a1), "r"(a2), "r"(a3), "r"(b0), "r"(b1))

// ---------------- launch 3: HMMA edge GEMM (plain fp16), high occupancy ----------------
// Persistent blocks of 8 independent warps, 4 blocks/SM; warp-tile = 16 CSR edges.
// Prep: coalesced LDG.128 of u/v, h = lrelu(u+v) in fp16 to per-warp smem A tile.
// 32 HMMA per warp-tile, B fragments re-LDSM'd per ks (keeps regs <= 64 for occupancy).
// Segmented max via xor-shuffle over sorted dst; atomicMax flush per run.
__global__ void __launch_bounds__(256, 4) k_edge(const float* __restrict__ W2) {
    extern __shared__ __align__(16) char sm[];
    uint32_t sb = (uint32_t)__cvta_generic_to_shared(sm);
    int tid = threadIdx.x;
    int wid = tid >> 5;
    int lane = tid & 31;

    // ---- B = fp16(W2), [n][k] rows (col-major kxn for mma .col) ----
    for (int i = tid; i < 64 * 64; i += 256) {
        int n = i >> 6, k = i & 63;
        *(__half*)(sm + BOFF + n * BSTRIDE + k * 2) = __float2half_rn(W2[i]);
    }
    __syncthreads();
    uint32_t bBase = sb + BOFF + (uint32_t)((lane & 7) + ((lane >> 4) << 3)) * BSTRIDE
                   + (((lane >> 3) & 1) << 4);

    char* aw = sm + wid * AWARP;                      // this warp's A tile
    uint32_t aLane = sb + (uint32_t)(wid * AWARP)
                   + (uint32_t)(lane & 15) * ASTR + (((uint32_t)lane >> 4) << 4);
    int rq = lane >> 2;          // fragment row (0..7; +8 pair)
    int q2 = (lane & 3) * 2;     // fragment col pair base
    int pr = lane >> 3;          // prep row-within-group (0..3)
    int pc = lane & 7;           // prep col block (0..7)

    for (int tile = blockIdx.x; tile < NTILES; tile += gridDim.x) {
        int e0 = tile * TILE_M + wid * 16;
        int dmy = g_sd[e0 + (lane & 15)];
        int smy = g_ss[e0 + (lane & 15)];

        // ---- prep: coalesced gather u/v, h = lrelu(u+v), fp16 pack, STS ----
        #pragma unroll
        for (int it = 0; it < 4; it++) {
            int r = 4 * it + pr;
            int dn = __shfl_sync(0xFFFFFFFFu, dmy, r);
            int sn = __shfl_sync(0xFFFFFFFFu, smy, r);
            const float4* up = (const float4*)(g_u + dn * 64);
            const float4* vp = (const float4*)(g_v + sn * 64);
            char* rowp = aw + r * ASTR;
            #pragma unroll
            for (int h = 0; h < 2; h++) {
                float4 a = up[h * 8 + pc];
                float4 b = vp[h * 8 + pc];
                float h0 = a.x + b.x; h0 = fmaxf(h0, 0.01f * h0);
                float h1 = a.y + b.y; h1 = fmaxf(h1, 0.01f * h1);
                float h2 = a.z + b.z; h2 = fmaxf(h2, 0.01f * h2);
                float h3 = a.w + b.w; h3 = fmaxf(h3, 0.01f * h3);
                __half2 pA = __floats2half2_rn(h0, h1);
                __half2 pB = __floats2half2_rn(h2, h3);
                *(uint2*)(rowp + h * 64 + pc * 8) =
                    make_uint2(*(unsigned*)&pA, *(unsigned*)&pB);
            }
        }
        __syncwarp();

        // ---- K=64 fp16 GEMM: 32 HMMA; B re-LDSM'd per step (low reg pressure) ----
        float acc[8][4];
        #pragma unroll
        for (int ni = 0; ni < 8; ni++)
            acc[ni][0] = acc[ni][1] = acc[ni][2] = acc[ni][3] = 0.0f;

        #pragma unroll
        for (int ks = 0; ks < 4; ks++) {
            uint32_t a0, a1, a2, a3;
            LDSM4(a0, a1, a2, a3, aLane + (uint32_t)(ks * 32));
            #pragma unroll
            for (int np = 0; np < 4; np++) {
                uint32_t b0, b1, b2, b3;
                LDSM4(b0, b1, b2, b3,
                      bBase + (uint32_t)(ks * 32) + (uint32_t)(np * 16) * BSTRIDE);
                MMA16816(acc[2 * np],     a0, a1, a2, a3, b0, b1);
                MMA16816(acc[2 * np + 1], a0, a1, a2, a3, b2, b3);
            }
        }

        // ---- segmented max over sorted dst (runs within this warp's 16 rows) ----
        int dprev = __shfl_up_sync(0xFFFFFFFFu, dmy, 1);
        unsigned mask = __ballot_sync(0xFFFFFFFFu,
                            (lane < 16) && (lane == 0 || dmy != dprev)) & 0xFFFFu;
        int a = 0;
        while (a < 16) {
            unsigned rest = mask & ~((1u << (a + 1)) - 1u);
            int b = rest ? (__ffs(rest) - 1) : 16;
            int dseg = __shfl_sync(0xFFFFFFFFu, dmy, a);
            bool in0 = (rq >= a) && (rq < b);
            bool in1 = (rq + 8 >= a) && (rq + 8 < b);
            #pragma unroll
            for (int ni = 0; ni < 8; ni++) {
                float m0 = fmaxf(in0 ? acc[ni][0] : -CUDART_INF_F,
                                 in1 ? acc[ni][2] : -CUDART_INF_F);
                float m1 = fmaxf(in0 ? acc[ni][1] : -CUDART_INF_F,
                                 in1 ? acc[ni][3] : -CUDART_INF_F);
                #pragma unroll
                for (int off = 4; off <= 16; off <<= 1) {
                    m0 = fmaxf(m0, __shfl_xor_sync(0xFFFFFFFFu, m0, off));
                    m1 = fmaxf(m1, __shfl_xor_sync(0xFFFFFFFFu, m1, off));
                }
                if (rq == ni) {
                    atomicMax(&g_agg[dseg * 64 + ni * 8 + q2],     encf(m0));
                    atomicMax(&g_agg[dseg * 64 + ni * 8 + q2 + 1], encf(m1));
                }
            }
            a = b;
        }
        __syncwarp();
    }
}

// ---------------- launch 4: decode max, +b2, residual, relu; reset agg (x4 vec) ----------------
__global__ void __launch_bounds__(256) k_final(
    const float* __restrict__ x, const float* __restrict__ b2,
    float* __restrict__ out)
{
    int i4 = blockIdx.x * 256 + threadIdx.x;
    int c0 = (i4 * 4) & 63;
    uint4 u = *(const uint4*)(g_agg + i4 * 4);
    *(uint4*)(g_agg + i4 * 4) = make_uint4(0u, 0u, 0u, 0u);
    float4 xv = *(const float4*)(x + i4 * 4);
    float4 bv = *(const float4*)(b2 + c0);
    float4 o;
    {
        unsigned e;
        float m;
        e = u.x; m = (e >= 0x00800000u)
            ? __uint_as_float((e & 0x80000000u) ? (e & 0x7FFFFFFFu) : ~e) + bv.x : 0.0f;
        o.x = fmaxf(m + xv.x, 0.0f);
        e = u.y; m = (e >= 0x00800000u)
            ? __uint_as_float((e & 0x80000000u) ? (e & 0x7FFFFFFFu) : ~e) + bv.y : 0.0f;
        o.y = fmaxf(m + xv.y, 0.0f);
        e = u.z; m = (e >= 0x00800000u)
            ? __uint_as_float((e & 0x80000000u) ? (e & 0x7FFFFFFFu) : ~e) + bv.z : 0.0f;
        o.z = fmaxf(m + xv.z, 0.0f);
        e = u.w; m = (e >= 0x00800000u)
            ? __uint_as_float((e & 0x80000000u) ? (e & 0x7FFFFFFFu) : ~e) + bv.w : 0.0f;
        o.w = fmaxf(m + xv.w, 0.0f);
    }
    *(float4*)(out + i4 * 4) = o;
}

// ---------------- launch ----------------
extern "C" void kernel_launch(void* const* d_in, const int* in_sizes, int n_in,
                              void* d_out, int out_size) {
    const float* x  = (const float*)d_in[0];
    const void*  ei = d_in[1];
    const float* W1 = (const float*)d_in[2];
    const float* b1 = (const float*)d_in[3];
    const float* W2 = (const float*)d_in[4];
    const float* b2 = (const float*)d_in[5];
    float* out = (float*)d_out;

    cudaFuncSetAttribute(k_scannode, cudaFuncAttributeMaxDynamicSharedMemorySize, SN_DYNSZ);
    cudaFuncSetAttribute(k_edge, cudaFuncAttributeMaxDynamicSharedMemorySize, DYNSZ);

    k_hist    <<<NE / 512, 256>>>(ei);
    k_scannode<<<NN / 64 + 1, 1024, SN_DYNSZ>>>(x, W1, b1);
    k_scatter <<<NE / 512, 256>>>(ei);
    k_edge    <<<EDGE_GRID, 256, DYNSZ>>>(W2);
    k_final   <<<(NN * CC) / 1024, 256>>>(x, b2, out);
}

// round 11
// speedup vs baseline: 2.9735x; 1.2115x over previous
#include <cuda_runtime.h>
#include <cuda_fp16.h>
#include <math_constants.h>
#include <cstdint>

// Problem constants (fixed by the dataset)
#define CC    64
#define NB    2048
#define NT    20
#define NN    (NB * NT)          // 40960 nodes
#define NE    1310720            // edges
#define TILE_M 128               // edges per block tile (16 per warp)
#define NTILES (NE / TILE_M)     // 10240
#define EDGE_GRID 592            // persistent blocks (4 per SM)

// k_edge smem: per-warp A tiles + shared B (fp16)
#define ASTR    144              // A row: 64 fp16 (128B) + 16B pad
#define AWARP   (16 * ASTR)      // 2304 per warp
#define BOFF    (8 * AWARP)      // 18432
#define BSTRIDE 144              // B row: 64 fp16 + pad
#define DYNSZ   (BOFF + 64 * BSTRIDE)   // 27648

// k_scannode smem
#define SN_W1OFF  0                       // float2 W1p[64][65] = 33280B
#define SN_XTOFF  33280                   // float xs_t[64][68] = 17408B
#define SN_DYNSZ  (33280 + 17408)         // 50688

// -------- persistent device scratch (zero-initialized at load) --------
__device__ __align__(16) __half g_uh[NN * CC];   // fp16(x @ (W1a-W1b)^T + b1)
__device__ __align__(16) __half g_vh[NN * CC];   // fp16(x @ W1b^T)
__device__ int      g_deg[NN];        // zero-init; re-zeroed by k_scannode each run
__device__ int      g_rowptr[NN + 1];
__device__ int      g_rank[NE];       // rank of edge within its dst bucket
__device__ int2     g_sp[NE];         // (src, dst) sorted by dst
__device__ unsigned g_agg[NN * CC];   // monotone-encoded max; 0 = empty sentinel

// monotone float->unsigned encoding: order-preserving, finite values >= 0x00800000
__device__ __forceinline__ unsigned encf(float f) {
    unsigned b = __float_as_uint(f);
    return (b & 0x80000000u) ? ~b : (b | 0x80000000u);
}

// per-block edge_index dtype detection (int64 layout has odd 32-bit words all 0)
__device__ __forceinline__ int detect_is64(const void* ei, int* s_flag, int tid) {
    if (tid < 32) {
        int v = ((const int*)ei)[2 * tid + 1];
        unsigned m = __ballot_sync(0xFFFFFFFFu, v != 0);
        if (tid == 0) *s_flag = (m == 0u);
    }
    __syncthreads();
    return *s_flag;
}

__device__ __forceinline__ int load_idx(const void* ei, int pos, int is64) {
    if (is64) return (int)((const long long*)ei)[pos];
    return ((const int*)ei)[pos];
}

// ---------------- launch 0: degree histogram + per-edge rank ----------------
__global__ void __launch_bounds__(256) k_hist(const void* __restrict__ ei) {
    __shared__ int s_flag;
    int tid = threadIdx.x;
    int is64 = detect_is64(ei, &s_flag, tid);
    int e = (blockIdx.x * 256 + tid) * 2;
    #pragma unroll
    for (int j = 0; j < 2; j++) {
        int dst = load_idx(ei, NE + e + j, is64);
        if ((unsigned)dst < NN) g_rank[e + j] = atomicAdd(&g_deg[dst], 1);
    }
}

// ---------------- launch 1: block 0 = scan (+re-zero deg), others = node GEMM ----------------
__global__ void __launch_bounds__(1024) k_scannode(
    const float* __restrict__ x, const float* __restrict__ W1,
    const float* __restrict__ b1)
{
    extern __shared__ __align__(16) char snsm[];
    int tid = threadIdx.x;

    if (blockIdx.x == 0) {
        int* sums = (int*)snsm;
        int base = tid * 40;
        int s = 0;
        for (int i = 0; i < 40; i++) s += g_deg[base + i];
        sums[tid] = s;
        __syncthreads();
        for (int off = 1; off < 1024; off <<= 1) {
            int a = sums[tid];
            int b = (tid >= off) ? sums[tid - off] : 0;
            __syncthreads();
            sums[tid] = a + b;
            __syncthreads();
        }
        int run = (tid > 0) ? sums[tid - 1] : 0;
        for (int i = 0; i < 40; i++) {
            g_rowptr[base + i] = run;
            run += g_deg[base + i];
            g_deg[base + i] = 0;        // ready for next replay
        }
        if (tid == 1023) g_rowptr[NN] = run;
        return;
    }

    float2* W1p = (float2*)(snsm + SN_W1OFF);   // (W1a, W1b) pairs, stride 65
    float* xs_t = (float*)(snsm + SN_XTOFF);    // x transposed [k][n], stride 68
    for (int i = tid; i < 64 * 64; i += 1024) {
        int c = i >> 6, k = i & 63;
        W1p[c * 65 + k] = make_float2(W1[c * 128 + k], W1[c * 128 + 64 + k]);
    }
    int node0 = (blockIdx.x - 1) * 64;
    for (int i = tid; i < 64 * 64; i += 1024) {
        int n = i >> 6, k = i & 63;
        xs_t[k * 68 + n] = x[node0 * 64 + i];
    }
    __syncthreads();

    int c = tid & 63;
    int g = tid >> 6;
    float ua[4] = {0.f, 0.f, 0.f, 0.f};
    float vb[4] = {0.f, 0.f, 0.f, 0.f};
    #pragma unroll 8
    for (int k = 0; k < 64; k++) {
        float2 w = W1p[c * 65 + k];
        float4 xv = *(const float4*)(xs_t + k * 68 + g * 4);
        ua[0] = fmaf(xv.x, w.x, ua[0]); vb[0] = fmaf(xv.x, w.y, vb[0]);
        ua[1] = fmaf(xv.y, w.x, ua[1]); vb[1] = fmaf(xv.y, w.y, vb[1]);
        ua[2] = fmaf(xv.z, w.x, ua[2]); vb[2] = fmaf(xv.z, w.y, vb[2]);
        ua[3] = fmaf(xv.w, w.x, ua[3]); vb[3] = fmaf(xv.w, w.y, vb[3]);
    }
    float bc = b1[c];
    #pragma unroll
    for (int j = 0; j < 4; j++) {
        int n = node0 + g * 4 + j;
        g_uh[n * 64 + c] = __float2half_rn(ua[j] - vb[j] + bc);
        g_vh[n * 64 + c] = __float2half_rn(vb[j]);
    }
}

// ---------------- launch 2: scatter edges into CSR order (NO atomics) ----------------
__global__ void __launch_bounds__(256) k_scatter(const void* __restrict__ ei) {
    __shared__ int s_flag;
    int tid = threadIdx.x;
    int is64 = detect_is64(ei, &s_flag, tid);
    int e = (blockIdx.x * 256 + tid) * 2;
    #pragma unroll
    for (int j = 0; j < 2; j++) {
        int dst = load_idx(ei, NE + e + j, is64);
        int src = load_idx(ei, e + j, is64);
        if ((unsigned)dst < NN && (unsigned)src < NN) {
            int p = g_rowptr[dst] + g_rank[e + j];
            g_sp[p] = make_int2(src, dst);
        }
    }
}

#define LDSM4(r0, r1, r2, r3, addr) \
    asm volatile("ldmatrix.sync.aligned.m8n8.x4.shared.b16 {%0,%1,%2,%3}, [%4];" \
        : "=r"(r0), "=r"(r1), "=r"(r2), "=r"(r3) : "r"(addr))

#define MMA16816(acc, a0, a1, a2, a3, b0, b1) \
    asm volatile("mma.sync.aligned.m16n8k16.row.col.f32.f16.f16.f32 " \
        "{%0,%1,%2,%3}, {%4,%5,%6,%7}, {%8,%9}, {%0,%1,%2,%3};" \
        : "+f"((acc)[0]), "+f"((acc)[1]), "+f"((acc)[2]), "+f"((acc)[3]) \
        : "r"(a0), "r"(a1), "r"(a2), "r"(a3), "r"(b0), "r"(b1))

// ---------------- launch 3: HMMA edge GEMM (fp16 gather, half2 prep) ----------------
// Persistent blocks of 8 independent warps, 4 blocks/SM; warp-tile = 16 CSR edges.
// Prep: one LDG.128 per fp16 node row, h = lrelu(u+v) in half2 (3 ops per 4 ch),
// one STS.128 per row-group. 32 HMMA per warp-tile; shuffle seg-max; atomicMax flush.
__global__ void __launch_bounds__(256, 4) k_edge(const float* __restrict__ W2) {
    extern __shared__ __align__(16) char sm[];
    uint32_t sb = (uint32_t)__cvta_generic_to_shared(sm);
    int tid = threadIdx.x;
    int wid = tid >> 5;
    int lane = tid & 31;

    // ---- B = fp16(W2), [n][k] rows (col-major kxn for mma .col) ----
    for (int i = tid; i < 64 * 64; i += 256) {
        int n = i >> 6, k = i & 63;
        *(__half*)(sm + BOFF + n * BSTRIDE + k * 2) = __float2half_rn(W2[i]);
    }
    __syncthreads();
    uint32_t bBase = sb + BOFF + (uint32_t)((lane & 7) + ((lane >> 4) << 3)) * BSTRIDE
                   + (((lane >> 3) & 1) << 4);

    char* aw = sm + wid * AWARP;                      // this warp's A tile
    uint32_t aLane = sb + (uint32_t)(wid * AWARP)
                   + (uint32_t)(lane & 15) * ASTR + (((uint32_t)lane >> 4) << 4);
    int rq = lane >> 2;          // fragment row (0..7; +8 pair)
    int q2 = (lane & 3) * 2;     // fragment col pair base
    int pr = lane >> 3;          // prep row-within-group (0..3)
    int pc = lane & 7;           // prep 16B block within row (0..7)

    const __half2 c001 = __half2half2(__float2half_rn(0.01f));

    for (int tile = blockIdx.x; tile < NTILES; tile += gridDim.x) {
        int e0 = tile * TILE_M + wid * 16;
        int2 sd = g_sp[e0 + (lane & 15)];
        int smy = sd.x, dmy = sd.y;

        // ---- prep: fp16 gather, h = lrelu(u+v) in half2, STS.128 ----
        #pragma unroll
        for (int it = 0; it < 4; it++) {
            int r = 4 * it + pr;
            int dn = __shfl_sync(0xFFFFFFFFu, dmy, r);
            int sn = __shfl_sync(0xFFFFFFFFu, smy, r);
            uint4 uu = *(const uint4*)(g_uh + dn * 64 + pc * 8);
            uint4 vv = *(const uint4*)(g_vh + sn * 64 + pc * 8);
            uint4 hh;
            {
                __half2 h;
                h = __hadd2(*(__half2*)&uu.x, *(__half2*)&vv.x);
                h = __hmax2(h, __hmul2(h, c001)); hh.x = *(unsigned*)&h;
                h = __hadd2(*(__half2*)&uu.y, *(__half2*)&vv.y);
                h = __hmax2(h, __hmul2(h, c001)); hh.y = *(unsigned*)&h;
                h = __hadd2(*(__half2*)&uu.z, *(__half2*)&vv.z);
                h = __hmax2(h, __hmul2(h, c001)); hh.z = *(unsigned*)&h;
                h = __hadd2(*(__half2*)&uu.w, *(__half2*)&vv.w);
                h = __hmax2(h, __hmul2(h, c001)); hh.w = *(unsigned*)&h;
            }
            *(uint4*)(aw + r * ASTR + pc * 16) = hh;
        }
        __syncwarp();

        // ---- K=64 fp16 GEMM: 32 HMMA; B re-LDSM'd per step ----
        float acc[8][4];
        #pragma unroll
        for (int ni = 0; ni < 8; ni++)
            acc[ni][0] = acc[ni][1] = acc[ni][2] = acc[ni][3] = 0.0f;

        #pragma unroll
        for (int ks = 0; ks < 4; ks++) {
            uint32_t a0, a1, a2, a3;
            LDSM4(a0, a1, a2, a3, aLane + (uint32_t)(ks * 32));
            #pragma unroll
            for (int np = 0; np < 4; np++) {
                uint32_t b0, b1, b2, b3;
                LDSM4(b0, b1, b2, b3,
                      bBase + (uint32_t)(ks * 32) + (uint32_t)(np * 16) * BSTRIDE);
                MMA16816(acc[2 * np],     a0, a1, a2, a3, b0, b1);
                MMA16816(acc[2 * np + 1], a0, a1, a2, a3, b2, b3);
            }
        }

        // ---- segmented max over sorted dst (runs within this warp's 16 rows) ----
        int dprev = __shfl_up_sync(0xFFFFFFFFu, dmy, 1);
        unsigned mask = __ballot_sync(0xFFFFFFFFu,
                            (lane < 16) && (lane == 0 || dmy != dprev)) & 0xFFFFu;
        int a = 0;
        while (a < 16) {
            unsigned rest = mask & ~((1u << (a + 1)) - 1u);
            int b = rest ? (__ffs(rest) - 1) : 16;
            int dseg = __shfl_sync(0xFFFFFFFFu, dmy, a);
            bool in0 = (rq >= a) && (rq < b);
            bool in1 = (rq + 8 >= a) && (rq + 8 < b);
            #pragma unroll
            for (int ni = 0; ni < 8; ni++) {
                float m0 = fmaxf(in0 ? acc[ni][0] : -CUDART_INF_F,
                                 in1 ? acc[ni][2] : -CUDART_INF_F);
                float m1 = fmaxf(in0 ? acc[ni][1] : -CUDART_INF_F,
                                 in1 ? acc[ni][3] : -CUDART_INF_F);
                #pragma unroll
                for (int off = 4; off <= 16; off <<= 1) {
                    m0 = fmaxf(m0, __shfl_xor_sync(0xFFFFFFFFu, m0, off));
                    m1 = fmaxf(m1, __shfl_xor_sync(0xFFFFFFFFu, m1, off));
                }
                if (rq == ni) {
                    atomicMax(&g_agg[dseg * 64 + ni * 8 + q2],     encf(m0));
                    atomicMax(&g_agg[dseg * 64 + ni * 8 + q2 + 1], encf(m1));
                }
            }
            a = b;
        }
        __syncwarp();
    }
}

// ---------------- launch 4: decode max, +b2, residual, relu; reset agg (x4 vec) ----------------
__global__ void __launch_bounds__(256) k_final(
    const float* __restrict__ x, const float* __restrict__ b2,
    float* __restrict__ out)
{
    int i4 = blockIdx.x * 256 + threadIdx.x;
    int c0 = (i4 * 4) & 63;
    uint4 u = *(const uint4*)(g_agg + i4 * 4);
    *(uint4*)(g_agg + i4 * 4) = make_uint4(0u, 0u, 0u, 0u);
    float4 xv = *(const float4*)(x + i4 * 4);
    float4 bv = *(const float4*)(b2 + c0);
    float4 o;
    {
        unsigned e;
        float m;
        e = u.x; m = (e >= 0x00800000u)
            ? __uint_as_float((e & 0x80000000u) ? (e & 0x7FFFFFFFu) : ~e) + bv.x : 0.0f;
        o.x = fmaxf(m + xv.x, 0.0f);
        e = u.y; m = (e >= 0x00800000u)
            ? __uint_as_float((e & 0x80000000u) ? (e & 0x7FFFFFFFu) : ~e) + bv.y : 0.0f;
        o.y = fmaxf(m + xv.y, 0.0f);
        e = u.z; m = (e >= 0x00800000u)
            ? __uint_as_float((e & 0x80000000u) ? (e & 0x7FFFFFFFu) : ~e) + bv.z : 0.0f;
        o.z = fmaxf(m + xv.z, 0.0f);
        e = u.w; m = (e >= 0x00800000u)
            ? __uint_as_float((e & 0x80000000u) ? (e & 0x7FFFFFFFu) : ~e) + bv.w : 0.0f;
        o.w = fmaxf(m + xv.w, 0.0f);
    }
    *(float4*)(out + i4 * 4) = o;
}

// ---------------- launch ----------------
extern "C" void kernel_launch(void* const* d_in, const int* in_sizes, int n_in,
                              void* d_out, int out_size) {
    const float* x  = (const float*)d_in[0];
    const void*  ei = d_in[1];
    const float* W1 = (const float*)d_in[2];
    const float* b1 = (const float*)d_in[3];
    const float* W2 = (const float*)d_in[4];
    const float* b2 = (const float*)d_in[5];
    float* out = (float*)d_out;

    cudaFuncSetAttribute(k_scannode, cudaFuncAttributeMaxDynamicSharedMemorySize, SN_DYNSZ);
    cudaFuncSetAttribute(k_edge, cudaFuncAttributeMaxDynamicSharedMemorySize, DYNSZ);

    k_hist    <<<NE / 512, 256>>>(ei);
    k_scannode<<<NN / 64 + 1, 1024, SN_DYNSZ>>>(x, W1, b1);
    k_scatter <<<NE / 512, 256>>>(ei);
    k_edge    <<<EDGE_GRID, 256, DYNSZ>>>(W2);
    k_final   <<<(NN * CC) / 1024, 256>>>(x, b2, out);
}

// round 12
// speedup vs baseline: 3.0194x; 1.0154x over previous
#include <cuda_runtime.h>
#include <cuda_fp16.h>
#include <math_constants.h>
#include <cstdint>

// Problem constants (fixed by the dataset)
#define CC    64
#define NB    2048
#define NT    20
#define NN    (NB * NT)          // 40960 nodes
#define NE    1310720            // edges
#define EDGE_GRID 592            // persistent blocks
#define NWARPS (EDGE_GRID * 8)   // 4736 warps, one dst node each (strided)

// k_edge smem: per-warp A tiles + shared B (fp16)
#define ASTR    144              // A row: 64 fp16 (128B) + 16B pad
#define AWARP   (16 * ASTR)      // 2304 per warp
#define BOFF    (8 * AWARP)      // 18432
#define BSTRIDE 144              // B row: 64 fp16 + pad
#define DYNSZ   (BOFF + 64 * BSTRIDE)   // 27648

// k_scannode smem
#define SN_W1OFF  0                       // float2 W1p[64][65] = 33280B
#define SN_XTOFF  33280                   // float xs_t[64][68] = 17408B
#define SN_DYNSZ  (33280 + 17408)         // 50688

// -------- persistent device scratch (zero-initialized at load) --------
__device__ __align__(16) __half g_uh[NN * CC];   // fp16(x @ (W1a-W1b)^T + b1)
__device__ __align__(16) __half g_vh[NN * CC];   // fp16(x @ W1b^T)
__device__ int g_deg[NN];        // zero-init; re-zeroed by k_scannode each run
__device__ int g_rowptr[NN + 1];
__device__ int g_rank[NE];       // rank of edge within its dst bucket
__device__ int g_ss[NE];         // edge src sorted by dst (CSR)

// per-block edge_index dtype detection (int64 layout has odd 32-bit words all 0)
__device__ __forceinline__ int detect_is64(const void* ei, int* s_flag, int tid) {
    if (tid < 32) {
        int v = ((const int*)ei)[2 * tid + 1];
        unsigned m = __ballot_sync(0xFFFFFFFFu, v != 0);
        if (tid == 0) *s_flag = (m == 0u);
    }
    __syncthreads();
    return *s_flag;
}

// load 4 consecutive indices (16B/32B vectorized)
__device__ __forceinline__ void load_idx4(const void* ei, long long pos, int is64, int* d) {
    if (is64) {
        const uint4* p = (const uint4*)((const long long*)ei + pos);
        uint4 a = p[0], b = p[1];
        d[0] = (int)a.x; d[1] = (int)a.z; d[2] = (int)b.x; d[3] = (int)b.z;
    } else {
        uint4 a = *(const uint4*)((const int*)ei + pos);
        d[0] = (int)a.x; d[1] = (int)a.y; d[2] = (int)a.z; d[3] = (int)a.w;
    }
}

// ---------------- launch 0: degree histogram + per-edge rank (4 edges/thread) ----------------
__global__ void __launch_bounds__(256) k_hist(const void* __restrict__ ei) {
    __shared__ int s_flag;
    int tid = threadIdx.x;
    int is64 = detect_is64(ei, &s_flag, tid);
    int e = (blockIdx.x * 256 + tid) * 4;
    int d[4];
    load_idx4(ei, (long long)NE + e, is64, d);
    #pragma unroll
    for (int j = 0; j < 4; j++)
        if ((unsigned)d[j] < NN) g_rank[e + j] = atomicAdd(&g_deg[d[j]], 1);
}

// ---------------- launch 1: block 0 = scan (+re-zero deg), others = node GEMM ----------------
__global__ void __launch_bounds__(1024) k_scannode(
    const float* __restrict__ x, const float* __restrict__ W1,
    const float* __restrict__ b1)
{
    extern __shared__ __align__(16) char snsm[];
    int tid = threadIdx.x;

    if (blockIdx.x == 0) {
        int* sums = (int*)snsm;
        int base = tid * 40;
        int s = 0;
        for (int i = 0; i < 40; i++) s += g_deg[base + i];
        sums[tid] = s;
        __syncthreads();
        for (int off = 1; off < 1024; off <<= 1) {
            int a = sums[tid];
            int b = (tid >= off) ? sums[tid - off] : 0;
            __syncthreads();
            sums[tid] = a + b;
            __syncthreads();
        }
        int run = (tid > 0) ? sums[tid - 1] : 0;
        for (int i = 0; i < 40; i++) {
            g_rowptr[base + i] = run;
            run += g_deg[base + i];
            g_deg[base + i] = 0;        // ready for next replay
        }
        if (tid == 1023) g_rowptr[NN] = run;
        return;
    }

    float2* W1p = (float2*)(snsm + SN_W1OFF);   // (W1a, W1b) pairs, stride 65
    float* xs_t = (float*)(snsm + SN_XTOFF);    // x transposed [k][n], stride 68
    for (int i = tid; i < 64 * 64; i += 1024) {
        int c = i >> 6, k = i & 63;
        W1p[c * 65 + k] = make_float2(W1[c * 128 + k], W1[c * 128 + 64 + k]);
    }
    int node0 = (blockIdx.x - 1) * 64;
    for (int i = tid; i < 64 * 64; i += 1024) {
        int n = i >> 6, k = i & 63;
        xs_t[k * 68 + n] = x[node0 * 64 + i];
    }
    __syncthreads();

    int c = tid & 63;
    int g = tid >> 6;
    float ua[4] = {0.f, 0.f, 0.f, 0.f};
    float vb[4] = {0.f, 0.f, 0.f, 0.f};
    #pragma unroll 8
    for (int k = 0; k < 64; k++) {
        float2 w = W1p[c * 65 + k];
        float4 xv = *(const float4*)(xs_t + k * 68 + g * 4);
        ua[0] = fmaf(xv.x, w.x, ua[0]); vb[0] = fmaf(xv.x, w.y, vb[0]);
        ua[1] = fmaf(xv.y, w.x, ua[1]); vb[1] = fmaf(xv.y, w.y, vb[1]);
        ua[2] = fmaf(xv.z, w.x, ua[2]); vb[2] = fmaf(xv.z, w.y, vb[2]);
        ua[3] = fmaf(xv.w, w.x, ua[3]); vb[3] = fmaf(xv.w, w.y, vb[3]);
    }
    float bc = b1[c];
    #pragma unroll
    for (int j = 0; j < 4; j++) {
        int n = node0 + g * 4 + j;
        g_uh[n * 64 + c] = __float2half_rn(ua[j] - vb[j] + bc);
        g_vh[n * 64 + c] = __float2half_rn(vb[j]);
    }
}

// ---------------- launch 2: scatter src into CSR order (no atomics, 4/thread) ----------------
__global__ void __launch_bounds__(256) k_scatter(const void* __restrict__ ei) {
    __shared__ int s_flag;
    int tid = threadIdx.x;
    int is64 = detect_is64(ei, &s_flag, tid);
    int e = (blockIdx.x * 256 + tid) * 4;
    int d[4], s[4];
    load_idx4(ei, (long long)NE + e, is64, d);
    load_idx4(ei, (long long)e, is64, s);
    uint4 rk = *(const uint4*)(g_rank + e);
    unsigned r[4] = {rk.x, rk.y, rk.z, rk.w};
    #pragma unroll
    for (int j = 0; j < 4; j++)
        if ((unsigned)d[j] < NN && (unsigned)s[j] < NN)
            g_ss[g_rowptr[d[j]] + (int)r[j]] = s[j];
}

#define LDSM4(r0, r1, r2, r3, addr) \
    asm volatile("ldmatrix.sync.aligned.m8n8.x4.shared.b16 {%0,%1,%2,%3}, [%4];" \
        : "=r"(r0), "=r"(r1), "=r"(r2), "=r"(r3) : "r"(addr))

#define MMA16816(acc, a0, a1, a2, a3, b0, b1) \
    asm volatile("mma.sync.aligned.m16n8k16.row.col.f32.f16.f16.f32 " \
        "{%0,%1,%2,%3}, {%4,%5,%6,%7}, {%8,%9}, {%0,%1,%2,%3};" \
        : "+f"((acc)[0]), "+f"((acc)[1]), "+f"((acc)[2]), "+f"((acc)[3]) \
        : "r"(a0), "r"(a1), "r"(a2), "r"(a3), "r"(b0), "r"(b1))

// ---------------- launch 3: warp-per-dst HMMA edge GEMM, direct output ----------------
// Each warp owns whole dst nodes (strided): chunks of 16 edges -> MMA -> register fmax
// merge. One shuffle reduction + one coalesced STG per dst (bias+residual+relu fused).
// Tail rows duplicate a real edge of the same dst, so no masking is needed.
__global__ void __launch_bounds__(256, 3) k_edge(
    const float* __restrict__ W2, const float* __restrict__ x,
    const float* __restrict__ b2, float* __restrict__ out)
{
    extern __shared__ __align__(16) char sm[];
    uint32_t sb = (uint32_t)__cvta_generic_to_shared(sm);
    int tid = threadIdx.x;
    int wid = tid >> 5;
    int lane = tid & 31;

    // ---- B = fp16(W2), [n][k] rows (col-major kxn for mma .col) ----
    for (int i = tid; i < 64 * 64; i += 256) {
        int n = i >> 6, k = i & 63;
        *(__half*)(sm + BOFF + n * BSTRIDE + k * 2) = __float2half_rn(W2[i]);
    }
    __syncthreads();
    uint32_t bBase = sb + BOFF + (uint32_t)((lane & 7) + ((lane >> 4) << 3)) * BSTRIDE
                   + (((lane >> 3) & 1) << 4);

    char* aw = sm + wid * AWARP;                      // this warp's A tile
    uint32_t aLane = sb + (uint32_t)(wid * AWARP)
                   + (uint32_t)(lane & 15) * ASTR + (((uint32_t)lane >> 4) << 4);
    int rq = lane >> 2;          // fragment row (0..7; +8 pair)
    int q2 = (lane & 3) * 2;     // fragment col pair base
    int pr = lane >> 3;          // prep row-within-group (0..3)
    int pc = lane & 7;           // prep 16B block within row (0..7)

    const __half2 c001 = __half2half2(__float2half_rn(0.01f));
    float2 bpair = *(const float2*)(b2 + rq * 8 + q2);   // this lane's output cols
    int wgid = blockIdx.x * 8 + wid;

    for (int node = wgid; node < NN; node += NWARPS) {
        int beg = g_rowptr[node];
        int end = g_rowptr[node + 1];
        float2 xv = *(const float2*)(x + node * 64 + rq * 8 + q2);
        float* op = out + node * 64 + rq * 8 + q2;
        if (beg == end) {   // empty dst: agg = 0
            *(float2*)op = make_float2(fmaxf(xv.x, 0.0f), fmaxf(xv.y, 0.0f));
            continue;
        }
        uint4 uu = *(const uint4*)(g_uh + node * 64 + pc * 8);   // u row, per-dst

        float macc[8][2];
        #pragma unroll
        for (int ni = 0; ni < 8; ni++) { macc[ni][0] = -CUDART_INF_F; macc[ni][1] = -CUDART_INF_F; }

        for (int cb = beg; cb < end; cb += 16) {
            int sidx = cb + (lane & 15);
            if (sidx >= end) sidx = end - 1;       // duplicate a real edge (max-safe)
            int src = g_ss[sidx];

            // ---- prep: v gather, h = lrelu(u+v) in half2, STS.128 ----
            #pragma unroll
            for (int it = 0; it < 4; it++) {
                int r = 4 * it + pr;
                int sn = __shfl_sync(0xFFFFFFFFu, src, r);
                uint4 vv = *(const uint4*)(g_vh + sn * 64 + pc * 8);
                uint4 hh;
                {
                    __half2 h;
                    h = __hadd2(*(__half2*)&uu.x, *(__half2*)&vv.x);
                    h = __hmax2(h, __hmul2(h, c001)); hh.x = *(unsigned*)&h;
                    h = __hadd2(*(__half2*)&uu.y, *(__half2*)&vv.y);
                    h = __hmax2(h, __hmul2(h, c001)); hh.y = *(unsigned*)&h;
                    h = __hadd2(*(__half2*)&uu.z, *(__half2*)&vv.z);
                    h = __hmax2(h, __hmul2(h, c001)); hh.z = *(unsigned*)&h;
                    h = __hadd2(*(__half2*)&uu.w, *(__half2*)&vv.w);
                    h = __hmax2(h, __hmul2(h, c001)); hh.w = *(unsigned*)&h;
                }
                *(uint4*)(aw + r * ASTR + pc * 16) = hh;
            }
            __syncwarp();

            // ---- K=64 fp16 GEMM: 32 HMMA ----
            float acc[8][4];
            #pragma unroll
            for (int ni = 0; ni < 8; ni++)
                acc[ni][0] = acc[ni][1] = acc[ni][2] = acc[ni][3] = 0.0f;
            #pragma unroll
            for (int ks = 0; ks < 4; ks++) {
                uint32_t a0, a1, a2, a3;
                LDSM4(a0, a1, a2, a3, aLane + (uint32_t)(ks * 32));
                #pragma unroll
                for (int np = 0; np < 4; np++) {
                    uint32_t b0, b1, b2r, b3;
                    LDSM4(b0, b1, b2r, b3,
                          bBase + (uint32_t)(ks * 32) + (uint32_t)(np * 16) * BSTRIDE);
                    MMA16816(acc[2 * np],     a0, a1, a2, a3, b0, b1);
                    MMA16816(acc[2 * np + 1], a0, a1, a2, a3, b2r, b3);
                }
            }
            // ---- register merge (rows rq and rq+8 collapse per column) ----
            #pragma unroll
            for (int ni = 0; ni < 8; ni++) {
                macc[ni][0] = fmaxf(macc[ni][0], fmaxf(acc[ni][0], acc[ni][2]));
                macc[ni][1] = fmaxf(macc[ni][1], fmaxf(acc[ni][1], acc[ni][3]));
            }
            __syncwarp();   // LDSM reads done before next chunk's STS
        }

        // ---- one shuffle reduction per dst: max over the 8 row-groups ----
        float r0 = 0.0f, r1 = 0.0f;
        #pragma unroll
        for (int ni = 0; ni < 8; ni++) {
            float m0 = macc[ni][0], m1 = macc[ni][1];
            #pragma unroll
            for (int off = 4; off <= 16; off <<= 1) {
                m0 = fmaxf(m0, __shfl_xor_sync(0xFFFFFFFFu, m0, off));
                m1 = fmaxf(m1, __shfl_xor_sync(0xFFFFFFFFu, m1, off));
            }
            if (rq == ni) { r0 = m0; r1 = m1; }
        }
        // ---- fused epilogue: +b2, residual, relu, direct store ----
        *(float2*)op = make_float2(fmaxf(r0 + bpair.x + xv.x, 0.0f),
                                   fmaxf(r1 + bpair.y + xv.y, 0.0f));
    }
}

// ---------------- launch ----------------
extern "C" void kernel_launch(void* const* d_in, const int* in_sizes, int n_in,
                              void* d_out, int out_size) {
    const float* x  = (const float*)d_in[0];
    const void*  ei = d_in[1];
    const float* W1 = (const float*)d_in[2];
    const float* b1 = (const float*)d_in[3];
    const float* W2 = (const float*)d_in[4];
    const float* b2 = (const float*)d_in[5];
    float* out = (float*)d_out;

    cudaFuncSetAttribute(k_scannode, cudaFuncAttributeMaxDynamicSharedMemorySize, SN_DYNSZ);
    cudaFuncSetAttribute(k_edge, cudaFuncAttributeMaxDynamicSharedMemorySize, DYNSZ);

    k_hist    <<<NE / 1024, 256>>>(ei);
    k_scannode<<<NN / 64 + 1, 1024, SN_DYNSZ>>>(x, W1, b1);
    k_scatter <<<NE / 1024, 256>>>(ei);
    k_edge    <<<EDGE_GRID, 256, DYNSZ>>>(W2, x, b2, out);
}

// round 13
// speedup vs baseline: 3.3058x; 1.0949x over previous
#include <cuda_runtime.h>
#include <cuda_fp16.h>
#include <math_constants.h>
#include <cstdint>

// Problem constants (fixed by the dataset)
#define CC    64
#define NB    2048
#define NT    20
#define NN    (NB * NT)          // 40960 nodes
#define NE    1310720            // edges
#define EDGE_GRID 592            // persistent blocks (4 per SM)
#define NWARPS (EDGE_GRID * 8)   // 4736 warps, dst nodes strided across them

// k_edge smem: per-warp A tiles + shared B (fp16)
#define ASTR    144              // A row: 64 fp16 (128B) + 16B pad
#define AWARP   (16 * ASTR)      // 2304 per warp
#define BOFF    (8 * AWARP)      // 18432
#define BSTRIDE 144              // B row: 64 fp16 + pad
#define DYNSZ   (BOFF + 64 * BSTRIDE)   // 27648

// k_scannode smem
#define SN_W1OFF  0                       // float2 W1p[64][65] = 33280B
#define SN_XTOFF  33280                   // float xs_t[64][68] = 17408B
#define SN_DYNSZ  (33280 + 17408)         // 50688

// -------- persistent device scratch (zero-initialized at load) --------
__device__ __align__(16) __half g_uh[NN * CC];   // fp16(x @ (W1a-W1b)^T + b1)
__device__ __align__(16) __half g_vh[NN * CC];   // fp16(x @ W1b^T)
__device__ int g_deg[NN];        // zero-init; re-zeroed by k_scannode each run
__device__ int g_rowptr[NN + 1];
__device__ int g_rank[NE];       // rank of edge within its dst bucket
__device__ int g_ss[NE];         // edge src sorted by dst (CSR)

// per-block edge_index dtype detection (int64 layout has odd 32-bit words all 0)
__device__ __forceinline__ int detect_is64(const void* ei, int* s_flag, int tid) {
    if (tid < 32) {
        int v = ((const int*)ei)[2 * tid + 1];
        unsigned m = __ballot_sync(0xFFFFFFFFu, v != 0);
        if (tid == 0) *s_flag = (m == 0u);
    }
    __syncthreads();
    return *s_flag;
}

// load 4 consecutive indices (16B/32B vectorized)
__device__ __forceinline__ void load_idx4(const void* ei, long long pos, int is64, int* d) {
    if (is64) {
        const uint4* p = (const uint4*)((const long long*)ei + pos);
        uint4 a = p[0], b = p[1];
        d[0] = (int)a.x; d[1] = (int)a.z; d[2] = (int)b.x; d[3] = (int)b.z;
    } else {
        uint4 a = *(const uint4*)((const int*)ei + pos);
        d[0] = (int)a.x; d[1] = (int)a.y; d[2] = (int)a.z; d[3] = (int)a.w;
    }
}

// ---------------- launch 0: degree histogram + per-edge rank (4 edges/thread) ----------------
__global__ void __launch_bounds__(256) k_hist(const void* __restrict__ ei) {
    __shared__ int s_flag;
    int tid = threadIdx.x;
    int is64 = detect_is64(ei, &s_flag, tid);
    int e = (blockIdx.x * 256 + tid) * 4;
    int d[4];
    load_idx4(ei, (long long)NE + e, is64, d);
    #pragma unroll
    for (int j = 0; j < 4; j++)
        if ((unsigned)d[j] < NN) g_rank[e + j] = atomicAdd(&g_deg[d[j]], 1);
}

// ---------------- launch 1: block 0 = scan (+re-zero deg), others = node GEMM ----------------
__global__ void __launch_bounds__(1024) k_scannode(
    const float* __restrict__ x, const float* __restrict__ W1,
    const float* __restrict__ b1)
{
    extern __shared__ __align__(16) char snsm[];
    int tid = threadIdx.x;

    if (blockIdx.x == 0) {
        int* sums = (int*)snsm;
        int base = tid * 40;
        int s = 0;
        for (int i = 0; i < 40; i++) s += g_deg[base + i];
        sums[tid] = s;
        __syncthreads();
        for (int off = 1; off < 1024; off <<= 1) {
            int a = sums[tid];
            int b = (tid >= off) ? sums[tid - off] : 0;
            __syncthreads();
            sums[tid] = a + b;
            __syncthreads();
        }
        int run = (tid > 0) ? sums[tid - 1] : 0;
        for (int i = 0; i < 40; i++) {
            g_rowptr[base + i] = run;
            run += g_deg[base + i];
            g_deg[base + i] = 0;        // ready for next replay
        }
        if (tid == 1023) g_rowptr[NN] = run;
        return;
    }

    float2* W1p = (float2*)(snsm + SN_W1OFF);   // (W1a, W1b) pairs, stride 65
    float* xs_t = (float*)(snsm + SN_XTOFF);    // x transposed [k][n], stride 68
    for (int i = tid; i < 64 * 64; i += 1024) {
        int c = i >> 6, k = i & 63;
        W1p[c * 65 + k] = make_float2(W1[c * 128 + k], W1[c * 128 + 64 + k]);
    }
    int node0 = (blockIdx.x - 1) * 64;
    for (int i = tid; i < 64 * 64; i += 1024) {
        int n = i >> 6, k = i & 63;
        xs_t[k * 68 + n] = x[node0 * 64 + i];
    }
    __syncthreads();

    int c = tid & 63;
    int g = tid >> 6;
    float ua[4] = {0.f, 0.f, 0.f, 0.f};
    float vb[4] = {0.f, 0.f, 0.f, 0.f};
    #pragma unroll 8
    for (int k = 0; k < 64; k++) {
        float2 w = W1p[c * 65 + k];
        float4 xv = *(const float4*)(xs_t + k * 68 + g * 4);
        ua[0] = fmaf(xv.x, w.x, ua[0]); vb[0] = fmaf(xv.x, w.y, vb[0]);
        ua[1] = fmaf(xv.y, w.x, ua[1]); vb[1] = fmaf(xv.y, w.y, vb[1]);
        ua[2] = fmaf(xv.z, w.x, ua[2]); vb[2] = fmaf(xv.z, w.y, vb[2]);
        ua[3] = fmaf(xv.w, w.x, ua[3]); vb[3] = fmaf(xv.w, w.y, vb[3]);
    }
    float bc = b1[c];
    #pragma unroll
    for (int j = 0; j < 4; j++) {
        int n = node0 + g * 4 + j;
        g_uh[n * 64 + c] = __float2half_rn(ua[j] - vb[j] + bc);
        g_vh[n * 64 + c] = __float2half_rn(vb[j]);
    }
}

// ---------------- launch 2: scatter src into CSR order (no atomics, 4/thread) ----------------
__global__ void __launch_bounds__(256) k_scatter(const void* __restrict__ ei) {
    __shared__ int s_flag;
    int tid = threadIdx.x;
    int is64 = detect_is64(ei, &s_flag, tid);
    int e = (blockIdx.x * 256 + tid) * 4;
    int d[4], s[4];
    load_idx4(ei, (long long)NE + e, is64, d);
    load_idx4(ei, (long long)e, is64, s);
    uint4 rk = *(const uint4*)(g_rank + e);
    unsigned r[4] = {rk.x, rk.y, rk.z, rk.w};
    #pragma unroll
    for (int j = 0; j < 4; j++)
        if ((unsigned)d[j] < NN && (unsigned)s[j] < NN)
            g_ss[g_rowptr[d[j]] + (int)r[j]] = s[j];
}

#define LDSM4(r0, r1, r2, r3, addr) \
    asm volatile("ldmatrix.sync.aligned.m8n8.x4.shared.b16 {%0,%1,%2,%3}, [%4];" \
        : "=r"(r0), "=r"(r1), "=r"(r2), "=r"(r3) : "r"(addr))

#define MMA16816(acc, a0, a1, a2, a3, b0, b1) \
    asm volatile("mma.sync.aligned.m16n8k16.row.col.f32.f16.f16.f32 " \
        "{%0,%1,%2,%3}, {%4,%5,%6,%7}, {%8,%9}, {%0,%1,%2,%3};" \
        : "+f"((acc)[0]), "+f"((acc)[1]), "+f"((acc)[2]), "+f"((acc)[3]) \
        : "r"(a0), "r"(a1), "r"(a2), "r"(a3), "r"(b0), "r"(b1))

// ---------------- launch 3: warp-per-dst HMMA edge GEMM, direct output ----------------
// Each warp owns whole dst nodes (strided): chunks of 16 edges -> MMA -> register fmax
// merge -> one shuffle reduction + coalesced STG per dst (bias+residual+relu fused).
// A-fragments preloaded to registers (np-outer MMA, 8-reg transient acc) to fit 64 regs
// at 4 blocks/SM.
__global__ void __launch_bounds__(256, 4) k_edge(
    const float* __restrict__ W2, const float* __restrict__ x,
    const float* __restrict__ b2, float* __restrict__ out)
{
    extern __shared__ __align__(16) char sm[];
    uint32_t sb = (uint32_t)__cvta_generic_to_shared(sm);
    int tid = threadIdx.x;
    int wid = tid >> 5;
    int lane = tid & 31;

    // ---- B = fp16(W2), [n][k] rows (col-major kxn for mma .col) ----
    for (int i = tid; i < 64 * 64; i += 256) {
        int n = i >> 6, k = i & 63;
        *(__half*)(sm + BOFF + n * BSTRIDE + k * 2) = __float2half_rn(W2[i]);
    }
    __syncthreads();
    uint32_t bBase = sb + BOFF + (uint32_t)((lane & 7) + ((lane >> 4) << 3)) * BSTRIDE
                   + (((lane >> 3) & 1) << 4);

    char* aw = sm + wid * AWARP;                      // this warp's A tile
    uint32_t aLane = sb + (uint32_t)(wid * AWARP)
                   + (uint32_t)(lane & 15) * ASTR + (((uint32_t)lane >> 4) << 4);
    int rq = lane >> 2;          // fragment row (0..7; +8 pair)
    int q2 = (lane & 3) * 2;     // fragment col pair base
    int pr = lane >> 3;          // prep row-within-group (0..3)
    int pc = lane & 7;           // prep 16B block within row (0..7)

    const __half2 c001 = __half2half2(__float2half_rn(0.01f));
    float2 bpair = *(const float2*)(b2 + rq * 8 + q2);   // this lane's output cols
    int wgid = blockIdx.x * 8 + wid;

    for (int node = wgid; node < NN; node += NWARPS) {
        int beg = g_rowptr[node];
        int end = g_rowptr[node + 1];
        float2 xv = *(const float2*)(x + node * 64 + rq * 8 + q2);
        float* op = out + node * 64 + rq * 8 + q2;
        if (beg == end) {   // empty dst: agg = 0
            *(float2*)op = make_float2(fmaxf(xv.x, 0.0f), fmaxf(xv.y, 0.0f));
            continue;
        }
        uint4 uu = *(const uint4*)(g_uh + node * 64 + pc * 8);   // u row, per-dst

        float macc[8][2];
        #pragma unroll
        for (int ni = 0; ni < 8; ni++) { macc[ni][0] = -CUDART_INF_F; macc[ni][1] = -CUDART_INF_F; }

        for (int cb = beg; cb < end; cb += 16) {
            int sidx = cb + (lane & 15);
            if (sidx >= end) sidx = end - 1;       // duplicate a real edge (max-safe)
            int src = g_ss[sidx];

            // ---- prep: v gather, h = lrelu(u+v) in half2, STS.128 ----
            #pragma unroll
            for (int it = 0; it < 4; it++) {
                int r = 4 * it + pr;
                int sn = __shfl_sync(0xFFFFFFFFu, src, r);
                uint4 vv = *(const uint4*)(g_vh + sn * 64 + pc * 8);
                uint4 hh;
                {
                    __half2 h;
                    h = __hadd2(*(__half2*)&uu.x, *(__half2*)&vv.x);
                    h = __hmax2(h, __hmul2(h, c001)); hh.x = *(unsigned*)&h;
                    h = __hadd2(*(__half2*)&uu.y, *(__half2*)&vv.y);
                    h = __hmax2(h, __hmul2(h, c001)); hh.y = *(unsigned*)&h;
                    h = __hadd2(*(__half2*)&uu.z, *(__half2*)&vv.z);
                    h = __hmax2(h, __hmul2(h, c001)); hh.z = *(unsigned*)&h;
                    h = __hadd2(*(__half2*)&uu.w, *(__half2*)&vv.w);
                    h = __hmax2(h, __hmul2(h, c001)); hh.w = *(unsigned*)&h;
                }
                *(uint4*)(aw + r * ASTR + pc * 16) = hh;
            }
            __syncwarp();

            // ---- preload all A fragments (frees the tile early) ----
            uint32_t Af[4][4];
            #pragma unroll
            for (int ks = 0; ks < 4; ks++)
                LDSM4(Af[ks][0], Af[ks][1], Af[ks][2], Af[ks][3],
                      aLane + (uint32_t)(ks * 32));
            __syncwarp();   // A tile free: next chunk's STS may proceed after MMA issue

            // ---- np-outer MMA: transient 8-reg acc per 16-col group ----
            #pragma unroll
            for (int np = 0; np < 4; np++) {
                float acc0[4] = {0.f, 0.f, 0.f, 0.f};
                float acc1[4] = {0.f, 0.f, 0.f, 0.f};
                #pragma unroll
                for (int ks = 0; ks < 4; ks++) {
                    uint32_t b0, b1, b2r, b3;
                    LDSM4(b0, b1, b2r, b3,
                          bBase + (uint32_t)(ks * 32) + (uint32_t)(np * 16) * BSTRIDE);
                    MMA16816(acc0, Af[ks][0], Af[ks][1], Af[ks][2], Af[ks][3], b0, b1);
                    MMA16816(acc1, Af[ks][0], Af[ks][1], Af[ks][2], Af[ks][3], b2r, b3);
                }
                macc[2 * np][0]     = fmaxf(macc[2 * np][0],     fmaxf(acc0[0], acc0[2]));
                macc[2 * np][1]     = fmaxf(macc[2 * np][1],     fmaxf(acc0[1], acc0[3]));
                macc[2 * np + 1][0] = fmaxf(macc[2 * np + 1][0], fmaxf(acc1[0], acc1[2]));
                macc[2 * np + 1][1] = fmaxf(macc[2 * np + 1][1], fmaxf(acc1[1], acc1[3]));
            }
        }

        // ---- one shuffle reduction per dst: max over the 8 row-groups ----
        float r0 = 0.0f, r1 = 0.0f;
        #pragma unroll
        for (int ni = 0; ni < 8; ni++) {
            float m0 = macc[ni][0], m1 = macc[ni][1];
            #pragma unroll
            for (int off = 4; off <= 16; off <<= 1) {
                m0 = fmaxf(m0, __shfl_xor_sync(0xFFFFFFFFu, m0, off));
                m1 = fmaxf(m1, __shfl_xor_sync(0xFFFFFFFFu, m1, off));
            }
            if (rq == ni) { r0 = m0; r1 = m1; }
        }
        // ---- fused epilogue: +b2, residual, relu, direct store ----
        *(float2*)op = make_float2(fmaxf(r0 + bpair.x + xv.x, 0.0f),
                                   fmaxf(r1 + bpair.y + xv.y, 0.0f));
    }
}

// ---------------- launch ----------------
extern "C" void kernel_launch(void* const* d_in, const int* in_sizes, int n_in,
                              void* d_out, int out_size) {
    const float* x  = (const float*)d_in[0];
    const void*  ei = d_in[1];
    const float* W1 = (const float*)d_in[2];
    const float* b1 = (const float*)d_in[3];
    const float* W2 = (const float*)d_in[4];
    const float* b2 = (const float*)d_in[5];
    float* out = (float*)d_out;

    cudaFuncSetAttribute(k_scannode, cudaFuncAttributeMaxDynamicSharedMemorySize, SN_DYNSZ);
    cudaFuncSetAttribute(k_edge, cudaFuncAttributeMaxDynamicSharedMemorySize, DYNSZ);

    k_hist    <<<NE / 1024, 256>>>(ei);
    k_scannode<<<NN / 64 + 1, 1024, SN_DYNSZ>>>(x, W1, b1);
    k_scatter <<<NE / 1024, 256>>>(ei);
    k_edge    <<<EDGE_GRID, 256, DYNSZ>>>(W2, x, b2, out);
}